// round 6
// baseline (speedup 1.0000x reference)
#include <cuda_runtime.h>
#include <cstdint>

// Problem constants
#define BSZ 8
#define SEQT 256
#define NJ 24
#define DIM 512
#define NH 8
#define HD 64

#define QKV_ELEMS (BSZ * NJ * SEQT * DIM)  // 25,165,824
#define W_ELEMS   (NJ * DIM * DIM)         // 6,291,456

// Scratch (layout [b][j][t][e], e = h*HD + d)
__device__ float g_Q[QKV_ELEMS];
__device__ float g_K[QKV_ELEMS];
__device__ float g_V[QKV_ELEMS];
__device__ float g_O[QKV_ELEMS];

// tf32-pre-rounded inputs (RNA once; GEMM mma truncation is then exact)
__device__ float g_Xc[QKV_ELEMS];
__device__ float g_Wqc[W_ELEMS];
__device__ float g_Wkc[W_ELEMS];
__device__ float g_Wvc[W_ELEMS];
__device__ float g_Woc[DIM * DIM];

__device__ __forceinline__ float to_tf32(float x) {
    uint32_t r;
    asm("cvt.rna.tf32.f32 %0, %1;" : "=r"(r) : "f"(x));
    return __uint_as_float(r);
}
__device__ __forceinline__ uint32_t f2tf(float x) {
    uint32_t r;
    asm("cvt.rna.tf32.f32 %0, %1;" : "=r"(r) : "f"(x));
    return r;
}

__device__ __forceinline__ void mma_tf32(
    float& c0, float& c1, float& c2, float& c3,
    uint32_t a0, uint32_t a1, uint32_t a2, uint32_t a3,
    uint32_t b0, uint32_t b1)
{
    asm volatile(
        "mma.sync.aligned.m16n8k8.row.col.f32.tf32.tf32.f32 "
        "{%0,%1,%2,%3}, {%4,%5,%6,%7}, {%8,%9}, {%0,%1,%2,%3};\n"
        : "+f"(c0), "+f"(c1), "+f"(c2), "+f"(c3)
        : "r"(a0), "r"(a1), "r"(a2), "r"(a3), "r"(b0), "r"(b1));
}

__device__ __forceinline__ void cpasync16(uint32_t dst, const float* src) {
    asm volatile("cp.async.ca.shared.global [%0], [%1], 16;\n"
                 :: "r"(dst), "l"(src));
}
#define CP_COMMIT() asm volatile("cp.async.commit_group;\n" ::: "memory")
#define CP_WAIT(N)  asm volatile("cp.async.wait_group %0;\n" :: "n"(N) : "memory")

// ---------------------------------------------------------------------------
// Kernel 0: RNA tf32 rounding pre-pass (pure bandwidth)
// ---------------------------------------------------------------------------
__global__ __launch_bounds__(256)
void cvt_kernel(const float4* __restrict__ in, float4* __restrict__ out, int n4)
{
    int i = blockIdx.x * blockDim.x + threadIdx.x;
    if (i < n4) {
        float4 v = in[i];
        out[i] = make_float4(to_tf32(v.x), to_tf32(v.y), to_tf32(v.z), to_tf32(v.w));
    }
}

// ---------------------------------------------------------------------------
// Kernel 1: per-joint Q/K/V projection, tf32 mma + cp.async double buffer.
// Block 128x128, BK=32, 256 threads (8 warps, 2Mx4N, warp 64x32), 2 CTAs/SM.
// A smem [128][36] row-major (bank 4g+q); B smem [32][136] k-major (bank 8q+g).
// grid: (4, 16, 72)
// ---------------------------------------------------------------------------
#define AST 36
#define BST 136
#define ABUF (128 * AST)            // 4608 floats
#define BBUF (32 * BST)             // 4352 floats
#define QSTG (ABUF + BBUF)          // 8960 floats
#define QKV_SMEM (2 * QSTG * 4)     // 71680 bytes

__global__ __launch_bounds__(256, 2)
void qkv_tc_kernel()
{
    extern __shared__ float smem[];
    const uint32_t sbase = (uint32_t)__cvta_generic_to_shared(smem);

    const int nt = blockIdx.x;
    const int mt = blockIdx.y;
    const int z  = blockIdx.z;
    const int j  = z % NJ;
    const int p  = z / NJ;

    const float* W = (p == 0) ? g_Wqc : ((p == 1) ? g_Wkc : g_Wvc);
    float* outp    = (p == 0) ? g_Q : ((p == 1) ? g_K : g_V);

    const int tid  = threadIdx.x;
    const int wid  = tid >> 5;
    const int lane = tid & 31;
    const int wm   = (wid >> 2) * 64;
    const int wn   = (wid & 3) * 32;
    const int grp  = lane >> 2;
    const int qd   = lane & 3;

    const int arow = tid >> 3;      // 0..31
    const int ac   = tid & 7;
    const int bkr  = tid >> 5;      // 0..7
    const int bc   = tid & 31;

    const size_t wbase = (size_t)j * DIM * DIM + nt * 128;

    float acc[4][4][4];
#pragma unroll
    for (int i = 0; i < 4; i++)
#pragma unroll
        for (int jn = 0; jn < 4; jn++)
#pragma unroll
            for (int c = 0; c < 4; c++)
                acc[i][jn][c] = 0.0f;

    auto stage = [&](int kb, int buf) {
        uint32_t abase = sbase + buf * (QSTG * 4);
        uint32_t bbase = abase + ABUF * 4;
#pragma unroll
        for (int l = 0; l < 4; l++) {
            int row = arow + l * 32;
            cpasync16(abase + row * (AST * 4) + ac * 16,
                      g_Xc + ((size_t)(mt * 128 + row) * NJ + j) * DIM + kb * 32 + ac * 4);
        }
#pragma unroll
        for (int l = 0; l < 4; l++) {
            int kr = bkr + l * 8;
            cpasync16(bbase + kr * (BST * 4) + bc * 16,
                      W + wbase + (size_t)(kb * 32 + kr) * DIM + bc * 4);
        }
    };

    stage(0, 0);
    CP_COMMIT();

    int buf = 0;
    for (int kb = 0; kb < DIM / 32; kb++) {
        if (kb + 1 < DIM / 32) {
            stage(kb + 1, buf ^ 1);
            CP_COMMIT();
            CP_WAIT(1);
        } else {
            CP_WAIT(0);
        }
        __syncthreads();

        const uint32_t* Asu = (const uint32_t*)(smem + buf * QSTG);
        const uint32_t* Bsu = (const uint32_t*)(smem + buf * QSTG + ABUF);

#pragma unroll
        for (int kk = 0; kk < 4; kk++) {
            const int k = kk * 8;
            uint32_t a[4][4];
#pragma unroll
            for (int i = 0; i < 4; i++) {
                int r0 = wm + 16 * i + grp;
                a[i][0] = Asu[r0 * AST + k + qd];
                a[i][1] = Asu[(r0 + 8) * AST + k + qd];
                a[i][2] = Asu[r0 * AST + k + qd + 4];
                a[i][3] = Asu[(r0 + 8) * AST + k + qd + 4];
            }
            uint32_t b[4][2];
#pragma unroll
            for (int jn = 0; jn < 4; jn++) {
                int n = wn + 8 * jn + grp;
                b[jn][0] = Bsu[(k + qd) * BST + n];
                b[jn][1] = Bsu[(k + qd + 4) * BST + n];
            }
#pragma unroll
            for (int i = 0; i < 4; i++)
#pragma unroll
                for (int jn = 0; jn < 4; jn++)
                    mma_tf32(acc[i][jn][0], acc[i][jn][1], acc[i][jn][2], acc[i][jn][3],
                             a[i][0], a[i][1], a[i][2], a[i][3],
                             b[jn][0], b[jn][1]);
        }
        __syncthreads();
        buf ^= 1;
    }

    // Epilogue: store to [b][j][t][e]
#pragma unroll
    for (int i = 0; i < 4; i++) {
        int m = mt * 128 + wm + 16 * i + grp;
        int b = m >> 8;
        int t = m & (SEQT - 1);
        size_t base0 = (((size_t)(b * NJ + j) * SEQT) + t) * DIM + nt * 128 + wn;
        size_t base1 = base0 + (size_t)8 * DIM;
#pragma unroll
        for (int jn = 0; jn < 4; jn++) {
            int col = 8 * jn + 2 * qd;
            *(float2*)&outp[base0 + col] = make_float2(acc[i][jn][0], acc[i][jn][1]);
            *(float2*)&outp[base1 + col] = make_float2(acc[i][jn][2], acc[i][jn][3]);
        }
    }
}

// ---------------------------------------------------------------------------
// Kernel 2: flash-style tensor-core attention (unchanged except tf32-rounded
// output store, so proj can cp.async raw).
// ---------------------------------------------------------------------------
#define KS_STRIDE 68
#define VT_STRIDE 260
#define ATT_SMEM_FLOATS (2 * SEQT * KS_STRIDE + HD * VT_STRIDE)  // 51456
#define ATT_SMEM (ATT_SMEM_FLOATS * 4)                           // 205824 B

__global__ __launch_bounds__(512)
void attn_tc_kernel()
{
    extern __shared__ float sm[];
    float* Qs = sm;
    float* Ks = sm + SEQT * KS_STRIDE;
    float* Vt = sm + 2 * SEQT * KS_STRIDE;

    const int bjh = blockIdx.x;
    const int h   = bjh & (NH - 1);
    const int bj  = bjh >> 3;
    const int tid  = threadIdx.x;
    const int wid  = tid >> 5;
    const int lane = tid & 31;
    const int grp  = lane >> 2;
    const int qd   = lane & 3;
    const int m0   = wid * 16;

    const size_t base = (size_t)bj * SEQT * DIM + h * HD;
    const float* qg = g_Q + base;
    const float* kg = g_K + base;
    const float* vg = g_V + base;

#pragma unroll
    for (int l = 0; l < 8; l++) {
        int idx = tid + l * 512;
        int s  = idx >> 4;
        int dq = (idx & 15) * 4;
        float4 q = *(const float4*)(qg + (size_t)s * DIM + dq);
        float* dst = &Qs[s * KS_STRIDE + dq];
        dst[0] = to_tf32(q.x * 0.125f); dst[1] = to_tf32(q.y * 0.125f);
        dst[2] = to_tf32(q.z * 0.125f); dst[3] = to_tf32(q.w * 0.125f);
        float4 k = *(const float4*)(kg + (size_t)s * DIM + dq);
        float* dk = &Ks[s * KS_STRIDE + dq];
        dk[0] = to_tf32(k.x); dk[1] = to_tf32(k.y);
        dk[2] = to_tf32(k.z); dk[3] = to_tf32(k.w);
    }
#pragma unroll
    for (int l = 0; l < 8; l++) {
        int idx = tid + l * 512;
        int d  = idx & 63;
        int s0 = (idx >> 6) * 4;
        float4 v;
        v.x = to_tf32(vg[(size_t)(s0 + 0) * DIM + d]);
        v.y = to_tf32(vg[(size_t)(s0 + 1) * DIM + d]);
        v.z = to_tf32(vg[(size_t)(s0 + 2) * DIM + d]);
        v.w = to_tf32(vg[(size_t)(s0 + 3) * DIM + d]);
        *(float4*)&Vt[d * VT_STRIDE + s0] = v;
    }
    __syncthreads();

    const uint32_t* QsU = (const uint32_t*)Qs;
    const uint32_t* KsU = (const uint32_t*)Ks;
    const uint32_t* VtU = (const uint32_t*)Vt;

    float oacc[8][4];
#pragma unroll
    for (int jn = 0; jn < 8; jn++)
#pragma unroll
        for (int c = 0; c < 4; c++) oacc[jn][c] = 0.0f;
    float mrow[2] = { -1e30f, -1e30f };
    float lrow[2] = { 0.0f, 0.0f };

    const int src1 = (lane & ~3) | (qd >> 1);
    const int src2 = src1 + 2;

    for (int ch = 0; ch < 4; ch++) {
        float sacc[8][4];
#pragma unroll
        for (int jn = 0; jn < 8; jn++)
#pragma unroll
            for (int c = 0; c < 4; c++) sacc[jn][c] = 0.0f;

#pragma unroll
        for (int kt = 0; kt < 8; kt++) {
            const int k = 8 * kt;
            int r0 = m0 + grp;
            uint32_t a0 = QsU[r0 * KS_STRIDE + k + qd];
            uint32_t a1 = QsU[(r0 + 8) * KS_STRIDE + k + qd];
            uint32_t a2 = QsU[r0 * KS_STRIDE + k + qd + 4];
            uint32_t a3 = QsU[(r0 + 8) * KS_STRIDE + k + qd + 4];
            uint32_t b[8][2];
#pragma unroll
            for (int jn = 0; jn < 8; jn++) {
                int n = ch * 64 + 8 * jn + grp;
                b[jn][0] = KsU[n * KS_STRIDE + k + qd];
                b[jn][1] = KsU[n * KS_STRIDE + k + qd + 4];
            }
#pragma unroll
            for (int jn = 0; jn < 8; jn++)
                mma_tf32(sacc[jn][0], sacc[jn][1], sacc[jn][2], sacc[jn][3],
                         a0, a1, a2, a3, b[jn][0], b[jn][1]);
        }

#pragma unroll
        for (int r = 0; r < 2; r++) {
            float mx = -1e30f;
#pragma unroll
            for (int jn = 0; jn < 8; jn++) {
                mx = fmaxf(mx, sacc[jn][2 * r]);
                mx = fmaxf(mx, sacc[jn][2 * r + 1]);
            }
            mx = fmaxf(mx, __shfl_xor_sync(0xffffffffu, mx, 1));
            mx = fmaxf(mx, __shfl_xor_sync(0xffffffffu, mx, 2));
            float mnew = fmaxf(mrow[r], mx);
            float scale = __expf(mrow[r] - mnew);
            mrow[r] = mnew;
            float ps = 0.0f;
#pragma unroll
            for (int jn = 0; jn < 8; jn++) {
                float p0 = __expf(sacc[jn][2 * r] - mnew);
                float p1 = __expf(sacc[jn][2 * r + 1] - mnew);
                sacc[jn][2 * r] = p0;
                sacc[jn][2 * r + 1] = p1;
                ps += p0 + p1;
                oacc[jn][2 * r] *= scale;
                oacc[jn][2 * r + 1] *= scale;
            }
            lrow[r] = lrow[r] * scale + ps;
        }

#pragma unroll
        for (int kt = 0; kt < 8; kt++) {
            float x0 = __shfl_sync(0xffffffffu, sacc[kt][0], src1);
            float x1 = __shfl_sync(0xffffffffu, sacc[kt][1], src1);
            float y0 = __shfl_sync(0xffffffffu, sacc[kt][2], src1);
            float y1 = __shfl_sync(0xffffffffu, sacc[kt][3], src1);
            float u0 = __shfl_sync(0xffffffffu, sacc[kt][0], src2);
            float u1 = __shfl_sync(0xffffffffu, sacc[kt][1], src2);
            float v0 = __shfl_sync(0xffffffffu, sacc[kt][2], src2);
            float v1 = __shfl_sync(0xffffffffu, sacc[kt][3], src2);
            uint32_t a0 = f2tf((qd & 1) ? x1 : x0);
            uint32_t a1 = f2tf((qd & 1) ? y1 : y0);
            uint32_t a2 = f2tf((qd & 1) ? u1 : u0);
            uint32_t a3 = f2tf((qd & 1) ? v1 : v0);
            const int k = ch * 64 + 8 * kt;
#pragma unroll
            for (int jn = 0; jn < 8; jn++) {
                int n = 8 * jn + grp;
                uint32_t b0 = VtU[n * VT_STRIDE + k + qd];
                uint32_t b1 = VtU[n * VT_STRIDE + k + qd + 4];
                mma_tf32(oacc[jn][0], oacc[jn][1], oacc[jn][2], oacc[jn][3],
                         a0, a1, a2, a3, b0, b1);
            }
        }
    }

    float inv[2];
#pragma unroll
    for (int r = 0; r < 2; r++) {
        float lr = lrow[r];
        lr += __shfl_xor_sync(0xffffffffu, lr, 1);
        lr += __shfl_xor_sync(0xffffffffu, lr, 2);
        inv[r] = 1.0f / lr;
    }
    float* o0 = g_O + base + (size_t)(m0 + grp) * DIM;
    float* o1 = g_O + base + (size_t)(m0 + grp + 8) * DIM;
#pragma unroll
    for (int jn = 0; jn < 8; jn++) {
        int col = 8 * jn + 2 * qd;
        // store tf32-rounded so proj can consume via cp.async with exact mma
        *(float2*)&o0[col] = make_float2(to_tf32(oacc[jn][0] * inv[0]),
                                         to_tf32(oacc[jn][1] * inv[0]));
        *(float2*)&o1[col] = make_float2(to_tf32(oacc[jn][2] * inv[1]),
                                         to_tf32(oacc[jn][3] * inv[1]));
    }
}

// ---------------------------------------------------------------------------
// Kernel 3: output projection + bias, cp.async double buffer, 2 CTAs/SM.
// A smem [128][36], B smem [128][36] (Wo is [n][k] row-major). grid: (4, 48)
// ---------------------------------------------------------------------------
#define PBUF (128 * AST)                 // 4608 floats
#define PSTG (2 * PBUF)                  // 9216 floats (A + B)
#define PROJ_SMEM (2 * PSTG * 4)         // 73728 bytes

__global__ __launch_bounds__(256, 2)
void proj_tc_kernel(const float* __restrict__ bo,
                    float* __restrict__ out)
{
    extern __shared__ float smem[];
    const uint32_t sbase = (uint32_t)__cvta_generic_to_shared(smem);

    const int nt = blockIdx.x;
    const int mt = blockIdx.y;

    const int tid  = threadIdx.x;
    const int wid  = tid >> 5;
    const int lane = tid & 31;
    const int wm   = (wid >> 2) * 64;
    const int wn   = (wid & 3) * 32;
    const int grp  = lane >> 2;
    const int qd   = lane & 3;

    const int arow = tid >> 3;
    const int ac   = tid & 7;

    float acc[4][4][4];
#pragma unroll
    for (int i = 0; i < 4; i++)
#pragma unroll
        for (int jn = 0; jn < 4; jn++)
#pragma unroll
            for (int c = 0; c < 4; c++)
                acc[i][jn][c] = 0.0f;

    auto stage = [&](int kb, int buf) {
        uint32_t abase = sbase + buf * (PSTG * 4);
        uint32_t bbase = abase + PBUF * 4;
#pragma unroll
        for (int l = 0; l < 4; l++) {
            int row = arow + l * 32;
            cpasync16(abase + row * (AST * 4) + ac * 16,
                      g_O + (size_t)(mt * 128 + row) * DIM + kb * 32 + ac * 4);
        }
#pragma unroll
        for (int l = 0; l < 4; l++) {
            int n = arow + l * 32;
            cpasync16(bbase + n * (AST * 4) + ac * 16,
                      g_Woc + (size_t)(nt * 128 + n) * DIM + kb * 32 + ac * 4);
        }
    };

    stage(0, 0);
    CP_COMMIT();

    int buf = 0;
    for (int kb = 0; kb < DIM / 32; kb++) {
        if (kb + 1 < DIM / 32) {
            stage(kb + 1, buf ^ 1);
            CP_COMMIT();
            CP_WAIT(1);
        } else {
            CP_WAIT(0);
        }
        __syncthreads();

        const uint32_t* Asu = (const uint32_t*)(smem + buf * PSTG);
        const uint32_t* Bsu = (const uint32_t*)(smem + buf * PSTG + PBUF);

#pragma unroll
        for (int kk = 0; kk < 4; kk++) {
            const int k = kk * 8;
            uint32_t a[4][4];
#pragma unroll
            for (int i = 0; i < 4; i++) {
                int r0 = wm + 16 * i + grp;
                a[i][0] = Asu[r0 * AST + k + qd];
                a[i][1] = Asu[(r0 + 8) * AST + k + qd];
                a[i][2] = Asu[r0 * AST + k + qd + 4];
                a[i][3] = Asu[(r0 + 8) * AST + k + qd + 4];
            }
            uint32_t b[4][2];
#pragma unroll
            for (int jn = 0; jn < 4; jn++) {
                int n = wn + 8 * jn + grp;
                b[jn][0] = Bsu[n * AST + k + qd];
                b[jn][1] = Bsu[n * AST + k + qd + 4];
            }
#pragma unroll
            for (int i = 0; i < 4; i++)
#pragma unroll
                for (int jn = 0; jn < 4; jn++)
                    mma_tf32(acc[i][jn][0], acc[i][jn][1], acc[i][jn][2], acc[i][jn][3],
                             a[i][0], a[i][1], a[i][2], a[i][3],
                             b[jn][0], b[jn][1]);
        }
        __syncthreads();
        buf ^= 1;
    }

#pragma unroll
    for (int i = 0; i < 4; i++) {
        int r = mt * 128 + wm + 16 * i + grp;
        int b = r / (NJ * SEQT);
        int rem = r - b * (NJ * SEQT);
        int jj = rem >> 8;
        int t  = rem & (SEQT - 1);
        size_t base0 = (((size_t)(b * SEQT + t) * NJ) + jj) * DIM + nt * 128 + wn;
        size_t base1 = base0 + (size_t)8 * NJ * DIM;
#pragma unroll
        for (int jn = 0; jn < 4; jn++) {
            int col = 8 * jn + 2 * qd;
            float2 bb = *(const float2*)(bo + nt * 128 + wn + col);
            *(float2*)&out[base0 + col] = make_float2(acc[i][jn][0] + bb.x,
                                                      acc[i][jn][1] + bb.y);
            *(float2*)&out[base1 + col] = make_float2(acc[i][jn][2] + bb.x,
                                                      acc[i][jn][3] + bb.y);
        }
    }
}

// ---------------------------------------------------------------------------
extern "C" void kernel_launch(void* const* d_in, const int* in_sizes, int n_in,
                              void* d_out, int out_size)
{
    const float* x  = (const float*)d_in[0];
    const float* Wq = (const float*)d_in[1];
    const float* Wk = (const float*)d_in[2];
    const float* Wv = (const float*)d_in[3];
    const float* Wo = (const float*)d_in[4];
    const float* bo = (const float*)d_in[5];
    float* out = (float*)d_out;

    float* xc;  cudaGetSymbolAddress((void**)&xc,  g_Xc);
    float* wqc; cudaGetSymbolAddress((void**)&wqc, g_Wqc);
    float* wkc; cudaGetSymbolAddress((void**)&wkc, g_Wkc);
    float* wvc; cudaGetSymbolAddress((void**)&wvc, g_Wvc);
    float* woc; cudaGetSymbolAddress((void**)&woc, g_Woc);

    // 0) RNA tf32 rounding pre-pass
    cvt_kernel<<<(QKV_ELEMS / 4 + 255) / 256, 256>>>((const float4*)x,  (float4*)xc,  QKV_ELEMS / 4);
    cvt_kernel<<<(W_ELEMS   / 4 + 255) / 256, 256>>>((const float4*)Wq, (float4*)wqc, W_ELEMS / 4);
    cvt_kernel<<<(W_ELEMS   / 4 + 255) / 256, 256>>>((const float4*)Wk, (float4*)wkc, W_ELEMS / 4);
    cvt_kernel<<<(W_ELEMS   / 4 + 255) / 256, 256>>>((const float4*)Wv, (float4*)wvc, W_ELEMS / 4);
    cvt_kernel<<<(DIM * DIM / 4 + 255) / 256, 256>>>((const float4*)Wo, (float4*)woc, DIM * DIM / 4);

    // 1) QKV projection
    cudaFuncSetAttribute(qkv_tc_kernel,
                         cudaFuncAttributeMaxDynamicSharedMemorySize, QKV_SMEM);
    dim3 g1(DIM / 128, (BSZ * SEQT) / 128, 3 * NJ);   // (4, 16, 72)
    qkv_tc_kernel<<<g1, 256, QKV_SMEM>>>();

    // 2) attention (tensor cores)
    cudaFuncSetAttribute(attn_tc_kernel,
                         cudaFuncAttributeMaxDynamicSharedMemorySize, ATT_SMEM);
    attn_tc_kernel<<<BSZ * NJ * NH, 512, ATT_SMEM>>>();

    // 3) output projection + bias
    cudaFuncSetAttribute(proj_tc_kernel,
                         cudaFuncAttributeMaxDynamicSharedMemorySize, PROJ_SMEM);
    dim3 g3(DIM / 128, (BSZ * SEQT * NJ) / 128);      // (4, 48)
    proj_tc_kernel<<<g3, 256, PROJ_SMEM>>>(bo, out);
}

// round 7
// speedup vs baseline: 1.1917x; 1.1917x over previous
#include <cuda_runtime.h>
#include <cstdint>

// Problem constants
#define BSZ 8
#define SEQT 256
#define NJ 24
#define DIM 512
#define NH 8
#define HD 64

#define QKV_ELEMS (BSZ * NJ * SEQT * DIM)  // 25,165,824

// Scratch (layout [b][j][t][e], e = h*HD + d)
__device__ float g_Q[QKV_ELEMS];
__device__ float g_K[QKV_ELEMS];
__device__ float g_V[QKV_ELEMS];
__device__ float g_O[QKV_ELEMS];

__device__ __forceinline__ float to_tf32(float x) {
    uint32_t r;
    asm("cvt.rna.tf32.f32 %0, %1;" : "=r"(r) : "f"(x));
    return __uint_as_float(r);
}
__device__ __forceinline__ uint32_t f2tf(float x) {
    uint32_t r;
    asm("cvt.rna.tf32.f32 %0, %1;" : "=r"(r) : "f"(x));
    return r;
}

__device__ __forceinline__ void mma_tf32(
    float& c0, float& c1, float& c2, float& c3,
    uint32_t a0, uint32_t a1, uint32_t a2, uint32_t a3,
    uint32_t b0, uint32_t b1)
{
    asm volatile(
        "mma.sync.aligned.m16n8k8.row.col.f32.tf32.tf32.f32 "
        "{%0,%1,%2,%3}, {%4,%5,%6,%7}, {%8,%9}, {%0,%1,%2,%3};\n"
        : "+f"(c0), "+f"(c1), "+f"(c2), "+f"(c3)
        : "r"(a0), "r"(a1), "r"(a2), "r"(a3), "r"(b0), "r"(b1));
}

// Smem stride 36 floats: frag LDS bank = (4*grp + qd) mod 32 -> conflict-free
#define SA 36
#define SB 36
#define BUF_FLOATS (128 * SA + 128 * SB)   // one buffer: A(128x32) + B(128x32)
#define GEMM_SMEM (2 * BUF_FLOATS * 4)     // 73728 bytes

// ---------------------------------------------------------------------------
// Kernel 1: per-joint Q/K/V projection, tf32 tensor cores.
// Block tile 128x128, BK=32, 512 threads = 16 warps (4M x 4N), warp 32x32.
// Double-buffered smem, register-prefetch pipeline. ~90 regs -> 4 warps/SMSP.
// grid: (4, 16, 72)
// ---------------------------------------------------------------------------
__global__ __launch_bounds__(512)
void qkv_tc_kernel(const float* __restrict__ x,
                   const float* __restrict__ Wq,
                   const float* __restrict__ Wk,
                   const float* __restrict__ Wv)
{
    extern __shared__ float smem[];

    const int nt = blockIdx.x;   // 0..3  (N/128)
    const int mt = blockIdx.y;   // 0..15 (M/128)
    const int z  = blockIdx.z;
    const int j  = z % NJ;
    const int p  = z / NJ;

    const float* W = (p == 0) ? Wq : ((p == 1) ? Wk : Wv);
    float* outp    = (p == 0) ? g_Q : ((p == 1) ? g_K : g_V);

    const int tid  = threadIdx.x;
    const int wid  = tid >> 5;
    const int lane = tid & 31;
    const int wm   = (wid >> 2) * 32;   // 0..96
    const int wn   = (wid & 3) * 32;    // 0..96
    const int grp  = lane >> 2;
    const int qd   = lane & 3;

    // staging task coords
    const int arow = tid >> 3;          // 0..63 (A rows arow, arow+64)
    const int ac   = tid & 7;           // float4 index along k
    const int bn   = tid & 127;         // B column n
    const int bkh  = tid >> 7;          // 0..3 (k-octet)

    const size_t wbase = (size_t)j * DIM * DIM + nt * 128;

    float acc[2][4][4];
#pragma unroll
    for (int i = 0; i < 2; i++)
#pragma unroll
        for (int jn = 0; jn < 4; jn++)
#pragma unroll
            for (int c = 0; c < 4; c++)
                acc[i][jn][c] = 0.0f;

    float pa[8];    // A prefetch: 2 float4
    float pb[8];    // B prefetch: 8 k-scalars of column bn

    auto loadA = [&](int k0) {
#pragma unroll
        for (int l = 0; l < 2; l++) {
            int row = arow + l * 64;
            float4 v = *(const float4*)(x +
                ((size_t)(mt * 128 + row) * NJ + j) * DIM + k0 + ac * 4);
            pa[l * 4 + 0] = v.x; pa[l * 4 + 1] = v.y;
            pa[l * 4 + 2] = v.z; pa[l * 4 + 3] = v.w;
        }
#pragma unroll
        for (int e = 0; e < 8; e++)
            pb[e] = W[wbase + (size_t)(k0 + bkh * 8 + e) * DIM + bn];
    };
    auto storeS = [&](float* Ab, float* Bb) {
#pragma unroll
        for (int l = 0; l < 2; l++) {
            int row = arow + l * 64;
            float* d = &Ab[row * SA + ac * 4];
            d[0] = to_tf32(pa[l * 4 + 0]); d[1] = to_tf32(pa[l * 4 + 1]);
            d[2] = to_tf32(pa[l * 4 + 2]); d[3] = to_tf32(pa[l * 4 + 3]);
        }
        float* d = &Bb[bn * SB + bkh * 8];
#pragma unroll
        for (int e = 0; e < 8; e++)
            d[e] = to_tf32(pb[e]);
    };

    loadA(0);
    storeS(smem, smem + 128 * SA);
    __syncthreads();

    int buf = 0;
    for (int kb = 0; kb < DIM / 32; kb++) {
        if (kb + 1 < DIM / 32) loadA((kb + 1) * 32);   // LDG in flight under MMAs

        const float* Ab = smem + buf * BUF_FLOATS;
        const float* Bb = Ab + 128 * SA;
        const uint32_t* Asu = (const uint32_t*)Ab;
        const uint32_t* Bsu = (const uint32_t*)Bb;

#pragma unroll
        for (int kk = 0; kk < 4; kk++) {
            const int k = kk * 8;
            uint32_t a[2][4];
#pragma unroll
            for (int i = 0; i < 2; i++) {
                int r0 = wm + 16 * i + grp;
                a[i][0] = Asu[r0 * SA + k + qd];
                a[i][1] = Asu[(r0 + 8) * SA + k + qd];
                a[i][2] = Asu[r0 * SA + k + qd + 4];
                a[i][3] = Asu[(r0 + 8) * SA + k + qd + 4];
            }
            uint32_t b[4][2];
#pragma unroll
            for (int jn = 0; jn < 4; jn++) {
                int n = wn + 8 * jn + grp;
                b[jn][0] = Bsu[n * SB + k + qd];
                b[jn][1] = Bsu[n * SB + k + qd + 4];
            }
#pragma unroll
            for (int i = 0; i < 2; i++)
#pragma unroll
                for (int jn = 0; jn < 4; jn++)
                    mma_tf32(acc[i][jn][0], acc[i][jn][1], acc[i][jn][2], acc[i][jn][3],
                             a[i][0], a[i][1], a[i][2], a[i][3],
                             b[jn][0], b[jn][1]);
        }

        if (kb + 1 < DIM / 32) {
            float* Ab2 = smem + (buf ^ 1) * BUF_FLOATS;
            storeS(Ab2, Ab2 + 128 * SA);
        }
        __syncthreads();
        buf ^= 1;
    }

    // Epilogue: store to [b][j][t][e]
#pragma unroll
    for (int i = 0; i < 2; i++) {
        int m = mt * 128 + wm + 16 * i + grp;
        int b = m >> 8;
        int t = m & (SEQT - 1);
        size_t base0 = (((size_t)(b * NJ + j) * SEQT) + t) * DIM + nt * 128 + wn;
        size_t base1 = base0 + (size_t)8 * DIM;   // row m+8 (same b,j; never crosses)
#pragma unroll
        for (int jn = 0; jn < 4; jn++) {
            int col = 8 * jn + 2 * qd;
            *(float2*)&outp[base0 + col] = make_float2(acc[i][jn][0], acc[i][jn][1]);
            *(float2*)&outp[base1 + col] = make_float2(acc[i][jn][2], acc[i][jn][3]);
        }
    }
}

// ---------------------------------------------------------------------------
// Kernel 2: flash-style tensor-core attention (R5, unchanged/passing).
// ---------------------------------------------------------------------------
#define KS_STRIDE 68
#define VT_STRIDE 260
#define ATT_SMEM_FLOATS (2 * SEQT * KS_STRIDE + HD * VT_STRIDE)  // 51456
#define ATT_SMEM (ATT_SMEM_FLOATS * 4)                           // 205824 B

__global__ __launch_bounds__(512)
void attn_tc_kernel()
{
    extern __shared__ float sm[];
    float* Qs = sm;
    float* Ks = sm + SEQT * KS_STRIDE;
    float* Vt = sm + 2 * SEQT * KS_STRIDE;

    const int bjh = blockIdx.x;
    const int h   = bjh & (NH - 1);
    const int bj  = bjh >> 3;
    const int tid  = threadIdx.x;
    const int wid  = tid >> 5;
    const int lane = tid & 31;
    const int grp  = lane >> 2;
    const int qd   = lane & 3;
    const int m0   = wid * 16;

    const size_t base = (size_t)bj * SEQT * DIM + h * HD;
    const float* qg = g_Q + base;
    const float* kg = g_K + base;
    const float* vg = g_V + base;

#pragma unroll
    for (int l = 0; l < 8; l++) {
        int idx = tid + l * 512;
        int s  = idx >> 4;
        int dq = (idx & 15) * 4;
        float4 q = *(const float4*)(qg + (size_t)s * DIM + dq);
        float* dst = &Qs[s * KS_STRIDE + dq];
        dst[0] = to_tf32(q.x * 0.125f); dst[1] = to_tf32(q.y * 0.125f);
        dst[2] = to_tf32(q.z * 0.125f); dst[3] = to_tf32(q.w * 0.125f);
        float4 k = *(const float4*)(kg + (size_t)s * DIM + dq);
        float* dk = &Ks[s * KS_STRIDE + dq];
        dk[0] = to_tf32(k.x); dk[1] = to_tf32(k.y);
        dk[2] = to_tf32(k.z); dk[3] = to_tf32(k.w);
    }
#pragma unroll
    for (int l = 0; l < 8; l++) {
        int idx = tid + l * 512;
        int d  = idx & 63;
        int s0 = (idx >> 6) * 4;
        float4 v;
        v.x = to_tf32(vg[(size_t)(s0 + 0) * DIM + d]);
        v.y = to_tf32(vg[(size_t)(s0 + 1) * DIM + d]);
        v.z = to_tf32(vg[(size_t)(s0 + 2) * DIM + d]);
        v.w = to_tf32(vg[(size_t)(s0 + 3) * DIM + d]);
        *(float4*)&Vt[d * VT_STRIDE + s0] = v;
    }
    __syncthreads();

    const uint32_t* QsU = (const uint32_t*)Qs;
    const uint32_t* KsU = (const uint32_t*)Ks;
    const uint32_t* VtU = (const uint32_t*)Vt;

    float oacc[8][4];
#pragma unroll
    for (int jn = 0; jn < 8; jn++)
#pragma unroll
        for (int c = 0; c < 4; c++) oacc[jn][c] = 0.0f;
    float mrow[2] = { -1e30f, -1e30f };
    float lrow[2] = { 0.0f, 0.0f };

    const int src1 = (lane & ~3) | (qd >> 1);
    const int src2 = src1 + 2;

    for (int ch = 0; ch < 4; ch++) {
        float sacc[8][4];
#pragma unroll
        for (int jn = 0; jn < 8; jn++)
#pragma unroll
            for (int c = 0; c < 4; c++) sacc[jn][c] = 0.0f;

#pragma unroll
        for (int kt = 0; kt < 8; kt++) {
            const int k = 8 * kt;
            int r0 = m0 + grp;
            uint32_t a0 = QsU[r0 * KS_STRIDE + k + qd];
            uint32_t a1 = QsU[(r0 + 8) * KS_STRIDE + k + qd];
            uint32_t a2 = QsU[r0 * KS_STRIDE + k + qd + 4];
            uint32_t a3 = QsU[(r0 + 8) * KS_STRIDE + k + qd + 4];
            uint32_t b[8][2];
#pragma unroll
            for (int jn = 0; jn < 8; jn++) {
                int n = ch * 64 + 8 * jn + grp;
                b[jn][0] = KsU[n * KS_STRIDE + k + qd];
                b[jn][1] = KsU[n * KS_STRIDE + k + qd + 4];
            }
#pragma unroll
            for (int jn = 0; jn < 8; jn++)
                mma_tf32(sacc[jn][0], sacc[jn][1], sacc[jn][2], sacc[jn][3],
                         a0, a1, a2, a3, b[jn][0], b[jn][1]);
        }

#pragma unroll
        for (int r = 0; r < 2; r++) {
            float mx = -1e30f;
#pragma unroll
            for (int jn = 0; jn < 8; jn++) {
                mx = fmaxf(mx, sacc[jn][2 * r]);
                mx = fmaxf(mx, sacc[jn][2 * r + 1]);
            }
            mx = fmaxf(mx, __shfl_xor_sync(0xffffffffu, mx, 1));
            mx = fmaxf(mx, __shfl_xor_sync(0xffffffffu, mx, 2));
            float mnew = fmaxf(mrow[r], mx);
            float scale = __expf(mrow[r] - mnew);
            mrow[r] = mnew;
            float ps = 0.0f;
#pragma unroll
            for (int jn = 0; jn < 8; jn++) {
                float p0 = __expf(sacc[jn][2 * r] - mnew);
                float p1 = __expf(sacc[jn][2 * r + 1] - mnew);
                sacc[jn][2 * r] = p0;
                sacc[jn][2 * r + 1] = p1;
                ps += p0 + p1;
                oacc[jn][2 * r] *= scale;
                oacc[jn][2 * r + 1] *= scale;
            }
            lrow[r] = lrow[r] * scale + ps;
        }

#pragma unroll
        for (int kt = 0; kt < 8; kt++) {
            float x0 = __shfl_sync(0xffffffffu, sacc[kt][0], src1);
            float x1 = __shfl_sync(0xffffffffu, sacc[kt][1], src1);
            float y0 = __shfl_sync(0xffffffffu, sacc[kt][2], src1);
            float y1 = __shfl_sync(0xffffffffu, sacc[kt][3], src1);
            float u0 = __shfl_sync(0xffffffffu, sacc[kt][0], src2);
            float u1 = __shfl_sync(0xffffffffu, sacc[kt][1], src2);
            float v0 = __shfl_sync(0xffffffffu, sacc[kt][2], src2);
            float v1 = __shfl_sync(0xffffffffu, sacc[kt][3], src2);
            uint32_t a0 = f2tf((qd & 1) ? x1 : x0);
            uint32_t a1 = f2tf((qd & 1) ? y1 : y0);
            uint32_t a2 = f2tf((qd & 1) ? u1 : u0);
            uint32_t a3 = f2tf((qd & 1) ? v1 : v0);
            const int k = ch * 64 + 8 * kt;
#pragma unroll
            for (int jn = 0; jn < 8; jn++) {
                int n = 8 * jn + grp;
                uint32_t b0 = VtU[n * VT_STRIDE + k + qd];
                uint32_t b1 = VtU[n * VT_STRIDE + k + qd + 4];
                mma_tf32(oacc[jn][0], oacc[jn][1], oacc[jn][2], oacc[jn][3],
                         a0, a1, a2, a3, b0, b1);
            }
        }
    }

    float inv[2];
#pragma unroll
    for (int r = 0; r < 2; r++) {
        float lr = lrow[r];
        lr += __shfl_xor_sync(0xffffffffu, lr, 1);
        lr += __shfl_xor_sync(0xffffffffu, lr, 2);
        inv[r] = 1.0f / lr;
    }
    float* o0 = g_O + base + (size_t)(m0 + grp) * DIM;
    float* o1 = g_O + base + (size_t)(m0 + grp + 8) * DIM;
#pragma unroll
    for (int jn = 0; jn < 8; jn++) {
        int col = 8 * jn + 2 * qd;
        *(float2*)&o0[col] = make_float2(oacc[jn][0] * inv[0], oacc[jn][1] * inv[0]);
        *(float2*)&o1[col] = make_float2(oacc[jn][2] * inv[1], oacc[jn][3] * inv[1]);
    }
}

// ---------------------------------------------------------------------------
// Kernel 3: output projection + bias, same 512-thread retile.
// B = Wo is [n][k] row-major: float4 staging (no transpose). grid: (4, 48)
// ---------------------------------------------------------------------------
__global__ __launch_bounds__(512)
void proj_tc_kernel(const float* __restrict__ Wo,
                    const float* __restrict__ bo,
                    float* __restrict__ out)
{
    extern __shared__ float smem[];

    const int nt = blockIdx.x;
    const int mt = blockIdx.y;

    const int tid  = threadIdx.x;
    const int wid  = tid >> 5;
    const int lane = tid & 31;
    const int wm   = (wid >> 2) * 32;
    const int wn   = (wid & 3) * 32;
    const int grp  = lane >> 2;
    const int qd   = lane & 3;

    const int arow = tid >> 3;   // 0..63
    const int ac   = tid & 7;

    float acc[2][4][4];
#pragma unroll
    for (int i = 0; i < 2; i++)
#pragma unroll
        for (int jn = 0; jn < 4; jn++)
#pragma unroll
            for (int c = 0; c < 4; c++)
                acc[i][jn][c] = 0.0f;

    float pa[8];
    float pb[8];

    auto loadA = [&](int k0) {
#pragma unroll
        for (int l = 0; l < 2; l++) {
            int row = arow + l * 64;
            float4 v = *(const float4*)(g_O +
                ((size_t)(mt * 128 + row)) * DIM + k0 + ac * 4);
            pa[l * 4 + 0] = v.x; pa[l * 4 + 1] = v.y;
            pa[l * 4 + 2] = v.z; pa[l * 4 + 3] = v.w;
        }
#pragma unroll
        for (int l = 0; l < 2; l++) {
            int n = arow + l * 64;
            float4 v = *(const float4*)(Wo +
                (size_t)(nt * 128 + n) * DIM + k0 + ac * 4);
            pb[l * 4 + 0] = v.x; pb[l * 4 + 1] = v.y;
            pb[l * 4 + 2] = v.z; pb[l * 4 + 3] = v.w;
        }
    };
    auto storeS = [&](float* Ab, float* Bb) {
#pragma unroll
        for (int l = 0; l < 2; l++) {
            int row = arow + l * 64;
            float* d = &Ab[row * SA + ac * 4];
            d[0] = to_tf32(pa[l * 4 + 0]); d[1] = to_tf32(pa[l * 4 + 1]);
            d[2] = to_tf32(pa[l * 4 + 2]); d[3] = to_tf32(pa[l * 4 + 3]);
        }
#pragma unroll
        for (int l = 0; l < 2; l++) {
            int n = arow + l * 64;
            float* d = &Bb[n * SB + ac * 4];
            d[0] = to_tf32(pb[l * 4 + 0]); d[1] = to_tf32(pb[l * 4 + 1]);
            d[2] = to_tf32(pb[l * 4 + 2]); d[3] = to_tf32(pb[l * 4 + 3]);
        }
    };

    loadA(0);
    storeS(smem, smem + 128 * SA);
    __syncthreads();

    int buf = 0;
    for (int kb = 0; kb < DIM / 32; kb++) {
        if (kb + 1 < DIM / 32) loadA((kb + 1) * 32);

        const float* Ab = smem + buf * BUF_FLOATS;
        const float* Bb = Ab + 128 * SA;
        const uint32_t* Asu = (const uint32_t*)Ab;
        const uint32_t* Bsu = (const uint32_t*)Bb;

#pragma unroll
        for (int kk = 0; kk < 4; kk++) {
            const int k = kk * 8;
            uint32_t a[2][4];
#pragma unroll
            for (int i = 0; i < 2; i++) {
                int r0 = wm + 16 * i + grp;
                a[i][0] = Asu[r0 * SA + k + qd];
                a[i][1] = Asu[(r0 + 8) * SA + k + qd];
                a[i][2] = Asu[r0 * SA + k + qd + 4];
                a[i][3] = Asu[(r0 + 8) * SA + k + qd + 4];
            }
            uint32_t b[4][2];
#pragma unroll
            for (int jn = 0; jn < 4; jn++) {
                int n = wn + 8 * jn + grp;
                b[jn][0] = Bsu[n * SB + k + qd];
                b[jn][1] = Bsu[n * SB + k + qd + 4];
            }
#pragma unroll
            for (int i = 0; i < 2; i++)
#pragma unroll
                for (int jn = 0; jn < 4; jn++)
                    mma_tf32(acc[i][jn][0], acc[i][jn][1], acc[i][jn][2], acc[i][jn][3],
                             a[i][0], a[i][1], a[i][2], a[i][3],
                             b[jn][0], b[jn][1]);
        }

        if (kb + 1 < DIM / 32) {
            float* Ab2 = smem + (buf ^ 1) * BUF_FLOATS;
            storeS(Ab2, Ab2 + 128 * SA);
        }
        __syncthreads();
        buf ^= 1;
    }

    // Epilogue with bias, remap r=(b*NJ+j)*T+t -> [b][t][j][e]
#pragma unroll
    for (int i = 0; i < 2; i++) {
        int r = mt * 128 + wm + 16 * i + grp;
        int b = r / (NJ * SEQT);
        int rem = r - b * (NJ * SEQT);
        int jj = rem >> 8;
        int t  = rem & (SEQT - 1);
        size_t base0 = (((size_t)(b * SEQT + t) * NJ) + jj) * DIM + nt * 128 + wn;
        size_t base1 = base0 + (size_t)8 * NJ * DIM;  // t+8 (same b, jj; never crosses)
#pragma unroll
        for (int jn = 0; jn < 4; jn++) {
            int col = 8 * jn + 2 * qd;
            float2 bb = *(const float2*)(bo + nt * 128 + wn + col);
            *(float2*)&out[base0 + col] = make_float2(acc[i][jn][0] + bb.x,
                                                      acc[i][jn][1] + bb.y);
            *(float2*)&out[base1 + col] = make_float2(acc[i][jn][2] + bb.x,
                                                      acc[i][jn][3] + bb.y);
        }
    }
}

// ---------------------------------------------------------------------------
extern "C" void kernel_launch(void* const* d_in, const int* in_sizes, int n_in,
                              void* d_out, int out_size)
{
    const float* x  = (const float*)d_in[0];
    const float* Wq = (const float*)d_in[1];
    const float* Wk = (const float*)d_in[2];
    const float* Wv = (const float*)d_in[3];
    const float* Wo = (const float*)d_in[4];
    const float* bo = (const float*)d_in[5];
    float* out = (float*)d_out;

    // 1) QKV projection
    cudaFuncSetAttribute(qkv_tc_kernel,
                         cudaFuncAttributeMaxDynamicSharedMemorySize, GEMM_SMEM);
    dim3 g1(DIM / 128, (BSZ * SEQT) / 128, 3 * NJ);   // (4, 16, 72)
    qkv_tc_kernel<<<g1, 512, GEMM_SMEM>>>(x, Wq, Wk, Wv);

    // 2) attention (tensor cores)
    cudaFuncSetAttribute(attn_tc_kernel,
                         cudaFuncAttributeMaxDynamicSharedMemorySize, ATT_SMEM);
    attn_tc_kernel<<<BSZ * NJ * NH, 512, ATT_SMEM>>>();

    // 3) output projection + bias
    cudaFuncSetAttribute(proj_tc_kernel,
                         cudaFuncAttributeMaxDynamicSharedMemorySize, GEMM_SMEM);
    dim3 g3(DIM / 128, (BSZ * SEQT * NJ) / 128);      // (4, 48)
    proj_tc_kernel<<<g3, 512, GEMM_SMEM>>>(Wo, bo, out);
}

// round 8
// speedup vs baseline: 1.4975x; 1.2565x over previous
#include <cuda_runtime.h>
#include <cuda_fp16.h>
#include <cstdint>

// Problem constants
#define BSZ 8
#define SEQT 256
#define NJ 24
#define DIM 512
#define NH 8
#define HD 64

#define QKV_ELEMS (BSZ * NJ * SEQT * DIM)  // 25,165,824

// Scratch (layout [b][j][t][e], e = h*HD + d)
__device__ float g_Q[QKV_ELEMS];
__device__ float g_K[QKV_ELEMS];
__device__ float g_V[QKV_ELEMS];
__device__ float g_O[QKV_ELEMS];

__device__ __forceinline__ float to_tf32(float x) {
    uint32_t r;
    asm("cvt.rna.tf32.f32 %0, %1;" : "=r"(r) : "f"(x));
    return __uint_as_float(r);
}
__device__ __forceinline__ uint32_t f2tf(float x) {
    uint32_t r;
    asm("cvt.rna.tf32.f32 %0, %1;" : "=r"(r) : "f"(x));
    return r;
}
__device__ __forceinline__ uint32_t pkh2(float x, float y) {
    __half2 h = __float22half2_rn(make_float2(x, y));
    return *(uint32_t*)&h;
}

__device__ __forceinline__ void mma_tf32(
    float& c0, float& c1, float& c2, float& c3,
    uint32_t a0, uint32_t a1, uint32_t a2, uint32_t a3,
    uint32_t b0, uint32_t b1)
{
    asm volatile(
        "mma.sync.aligned.m16n8k8.row.col.f32.tf32.tf32.f32 "
        "{%0,%1,%2,%3}, {%4,%5,%6,%7}, {%8,%9}, {%0,%1,%2,%3};\n"
        : "+f"(c0), "+f"(c1), "+f"(c2), "+f"(c3)
        : "r"(a0), "r"(a1), "r"(a2), "r"(a3), "r"(b0), "r"(b1));
}

__device__ __forceinline__ void mma_f16(
    float& c0, float& c1, float& c2, float& c3,
    uint32_t a0, uint32_t a1, uint32_t a2, uint32_t a3,
    uint32_t b0, uint32_t b1)
{
    asm volatile(
        "mma.sync.aligned.m16n8k16.row.col.f32.f16.f16.f32 "
        "{%0,%1,%2,%3}, {%4,%5,%6,%7}, {%8,%9}, {%0,%1,%2,%3};\n"
        : "+f"(c0), "+f"(c1), "+f"(c2), "+f"(c3)
        : "r"(a0), "r"(a1), "r"(a2), "r"(a3), "r"(b0), "r"(b1));
}

// fp16 GEMM smem: uint32(=half2 pair) arrays, stride 20 u32/row (16 data + 4 pad)
// Fragment LDS bank = (20*grp + qd + kp) mod 32 -> all 32 distinct (conflict-free)
#define SAU 20
#define ABUF_U (128 * SAU)           // 2560 u32
#define STG_U  (2 * ABUF_U)          // A + B = 5120 u32
// double buffered: 2 * 5120 * 4 = 40960 bytes (static shared)

// ---------------------------------------------------------------------------
// Kernel 1: per-joint Q/K/V projection, fp16 m16n8k16 tensor cores.
// Block tile 128x128, BK=32, 256 threads = 8 warps (2M x 4N), warp 64x32.
// Double-buffered smem, register-prefetch pipeline (R5-proven skeleton).
// grid: (4, 16, 72)
// ---------------------------------------------------------------------------
__global__ __launch_bounds__(256)
void qkv_tc_kernel(const float* __restrict__ x,
                   const float* __restrict__ Wq,
                   const float* __restrict__ Wk,
                   const float* __restrict__ Wv)
{
    __shared__ __align__(16) uint32_t smem[2 * STG_U];

    const int nt = blockIdx.x;   // 0..3  (N/128)
    const int mt = blockIdx.y;   // 0..15 (M/128)
    const int z  = blockIdx.z;
    const int j  = z % NJ;
    const int p  = z / NJ;

    const float* W = (p == 0) ? Wq : ((p == 1) ? Wk : Wv);
    float* outp    = (p == 0) ? g_Q : ((p == 1) ? g_K : g_V);

    const int tid  = threadIdx.x;
    const int wid  = tid >> 5;
    const int lane = tid & 31;
    const int wm   = (wid >> 2) * 64;   // 0 or 64
    const int wn   = (wid & 3) * 32;    // 0..96
    const int grp  = lane >> 2;
    const int qd   = lane & 3;

    // staging task coords
    const int arow = tid >> 3;          // 0..31 (A rows arow + 32*l)
    const int ac   = tid & 7;           // float4 index along k
    const int bn   = tid & 127;         // B column n
    const int bkh  = tid >> 7;          // 0/1: which 16-k half

    const size_t wbase = (size_t)j * DIM * DIM + nt * 128;

    float acc[4][4][4];
#pragma unroll
    for (int i = 0; i < 4; i++)
#pragma unroll
        for (int jn = 0; jn < 4; jn++)
#pragma unroll
            for (int c = 0; c < 4; c++)
                acc[i][jn][c] = 0.0f;

    float pa[16];   // A prefetch: 4 float4 (rows arow+32l)
    float pb[16];   // B prefetch: 16 consecutive k of column bn

    auto loadA = [&](int k0) {
#pragma unroll
        for (int l = 0; l < 4; l++) {
            int row = arow + l * 32;
            float4 v = *(const float4*)(x +
                ((size_t)(mt * 128 + row) * NJ + j) * DIM + k0 + ac * 4);
            pa[l * 4 + 0] = v.x; pa[l * 4 + 1] = v.y;
            pa[l * 4 + 2] = v.z; pa[l * 4 + 3] = v.w;
        }
#pragma unroll
        for (int e = 0; e < 16; e++)
            pb[e] = W[wbase + (size_t)(k0 + bkh * 16 + e) * DIM + bn];
    };
    auto storeS = [&](uint32_t* Ab, uint32_t* Bb) {
#pragma unroll
        for (int l = 0; l < 4; l++) {
            int row = arow + l * 32;
            uint32_t* d = &Ab[row * SAU + ac * 2];
            d[0] = pkh2(pa[l * 4 + 0], pa[l * 4 + 1]);
            d[1] = pkh2(pa[l * 4 + 2], pa[l * 4 + 3]);
        }
        // B column bn: 8 pair-cols starting at 8*bkh -> 2x STS.128, all banks/phase
        uint32_t* d = &Bb[bn * SAU + bkh * 8];
#pragma unroll
        for (int e = 0; e < 8; e++)
            d[e] = pkh2(pb[2 * e], pb[2 * e + 1]);
    };

    loadA(0);
    storeS(smem, smem + ABUF_U);
    __syncthreads();

    int buf = 0;
    for (int kb = 0; kb < DIM / 32; kb++) {
        if (kb + 1 < DIM / 32) loadA((kb + 1) * 32);   // LDG in flight under MMAs

        const uint32_t* Asu = smem + buf * STG_U;
        const uint32_t* Bsu = Asu + ABUF_U;

#pragma unroll
        for (int kk = 0; kk < 2; kk++) {
            const int kp = kk * 8;      // pair-column base (8 pairs = k16)
            uint32_t a[4][4];
#pragma unroll
            for (int i = 0; i < 4; i++) {
                int r0 = wm + 16 * i + grp;
                a[i][0] = Asu[r0 * SAU + kp + qd];
                a[i][1] = Asu[(r0 + 8) * SAU + kp + qd];
                a[i][2] = Asu[r0 * SAU + kp + qd + 4];
                a[i][3] = Asu[(r0 + 8) * SAU + kp + qd + 4];
            }
            uint32_t b[4][2];
#pragma unroll
            for (int jn = 0; jn < 4; jn++) {
                int n = wn + 8 * jn + grp;
                b[jn][0] = Bsu[n * SAU + kp + qd];
                b[jn][1] = Bsu[n * SAU + kp + qd + 4];
            }
#pragma unroll
            for (int i = 0; i < 4; i++)
#pragma unroll
                for (int jn = 0; jn < 4; jn++)
                    mma_f16(acc[i][jn][0], acc[i][jn][1], acc[i][jn][2], acc[i][jn][3],
                            a[i][0], a[i][1], a[i][2], a[i][3],
                            b[jn][0], b[jn][1]);
        }

        if (kb + 1 < DIM / 32) {
            uint32_t* Ab2 = smem + (buf ^ 1) * STG_U;
            storeS(Ab2, Ab2 + ABUF_U);
        }
        __syncthreads();
        buf ^= 1;
    }

    // Epilogue: store to [b][j][t][e]
#pragma unroll
    for (int i = 0; i < 4; i++) {
        int m = mt * 128 + wm + 16 * i + grp;
        int b = m >> 8;
        int t = m & (SEQT - 1);
        size_t base0 = (((size_t)(b * NJ + j) * SEQT) + t) * DIM + nt * 128 + wn;
        size_t base1 = base0 + (size_t)8 * DIM;   // row m+8 (same b,j)
#pragma unroll
        for (int jn = 0; jn < 4; jn++) {
            int col = 8 * jn + 2 * qd;
            *(float2*)&outp[base0 + col] = make_float2(acc[i][jn][0], acc[i][jn][1]);
            *(float2*)&outp[base1 + col] = make_float2(acc[i][jn][2], acc[i][jn][3]);
        }
    }
}

// ---------------------------------------------------------------------------
// Kernel 2: flash-style tensor-core attention (R5, unchanged/passing).
// ---------------------------------------------------------------------------
#define KS_STRIDE 68
#define VT_STRIDE 260
#define ATT_SMEM_FLOATS (2 * SEQT * KS_STRIDE + HD * VT_STRIDE)  // 51456
#define ATT_SMEM (ATT_SMEM_FLOATS * 4)                           // 205824 B

__global__ __launch_bounds__(512)
void attn_tc_kernel()
{
    extern __shared__ float sm[];
    float* Qs = sm;
    float* Ks = sm + SEQT * KS_STRIDE;
    float* Vt = sm + 2 * SEQT * KS_STRIDE;

    const int bjh = blockIdx.x;
    const int h   = bjh & (NH - 1);
    const int bj  = bjh >> 3;
    const int tid  = threadIdx.x;
    const int wid  = tid >> 5;
    const int lane = tid & 31;
    const int grp  = lane >> 2;
    const int qd   = lane & 3;
    const int m0   = wid * 16;

    const size_t base = (size_t)bj * SEQT * DIM + h * HD;
    const float* qg = g_Q + base;
    const float* kg = g_K + base;
    const float* vg = g_V + base;

#pragma unroll
    for (int l = 0; l < 8; l++) {
        int idx = tid + l * 512;
        int s  = idx >> 4;
        int dq = (idx & 15) * 4;
        float4 q = *(const float4*)(qg + (size_t)s * DIM + dq);
        float* dst = &Qs[s * KS_STRIDE + dq];
        dst[0] = to_tf32(q.x * 0.125f); dst[1] = to_tf32(q.y * 0.125f);
        dst[2] = to_tf32(q.z * 0.125f); dst[3] = to_tf32(q.w * 0.125f);
        float4 k = *(const float4*)(kg + (size_t)s * DIM + dq);
        float* dk = &Ks[s * KS_STRIDE + dq];
        dk[0] = to_tf32(k.x); dk[1] = to_tf32(k.y);
        dk[2] = to_tf32(k.z); dk[3] = to_tf32(k.w);
    }
#pragma unroll
    for (int l = 0; l < 8; l++) {
        int idx = tid + l * 512;
        int d  = idx & 63;
        int s0 = (idx >> 6) * 4;
        float4 v;
        v.x = to_tf32(vg[(size_t)(s0 + 0) * DIM + d]);
        v.y = to_tf32(vg[(size_t)(s0 + 1) * DIM + d]);
        v.z = to_tf32(vg[(size_t)(s0 + 2) * DIM + d]);
        v.w = to_tf32(vg[(size_t)(s0 + 3) * DIM + d]);
        *(float4*)&Vt[d * VT_STRIDE + s0] = v;
    }
    __syncthreads();

    const uint32_t* QsU = (const uint32_t*)Qs;
    const uint32_t* KsU = (const uint32_t*)Ks;
    const uint32_t* VtU = (const uint32_t*)Vt;

    float oacc[8][4];
#pragma unroll
    for (int jn = 0; jn < 8; jn++)
#pragma unroll
        for (int c = 0; c < 4; c++) oacc[jn][c] = 0.0f;
    float mrow[2] = { -1e30f, -1e30f };
    float lrow[2] = { 0.0f, 0.0f };

    const int src1 = (lane & ~3) | (qd >> 1);
    const int src2 = src1 + 2;

    for (int ch = 0; ch < 4; ch++) {
        float sacc[8][4];
#pragma unroll
        for (int jn = 0; jn < 8; jn++)
#pragma unroll
            for (int c = 0; c < 4; c++) sacc[jn][c] = 0.0f;

#pragma unroll
        for (int kt = 0; kt < 8; kt++) {
            const int k = 8 * kt;
            int r0 = m0 + grp;
            uint32_t a0 = QsU[r0 * KS_STRIDE + k + qd];
            uint32_t a1 = QsU[(r0 + 8) * KS_STRIDE + k + qd];
            uint32_t a2 = QsU[r0 * KS_STRIDE + k + qd + 4];
            uint32_t a3 = QsU[(r0 + 8) * KS_STRIDE + k + qd + 4];
            uint32_t b[8][2];
#pragma unroll
            for (int jn = 0; jn < 8; jn++) {
                int n = ch * 64 + 8 * jn + grp;
                b[jn][0] = KsU[n * KS_STRIDE + k + qd];
                b[jn][1] = KsU[n * KS_STRIDE + k + qd + 4];
            }
#pragma unroll
            for (int jn = 0; jn < 8; jn++)
                mma_tf32(sacc[jn][0], sacc[jn][1], sacc[jn][2], sacc[jn][3],
                         a0, a1, a2, a3, b[jn][0], b[jn][1]);
        }

#pragma unroll
        for (int r = 0; r < 2; r++) {
            float mx = -1e30f;
#pragma unroll
            for (int jn = 0; jn < 8; jn++) {
                mx = fmaxf(mx, sacc[jn][2 * r]);
                mx = fmaxf(mx, sacc[jn][2 * r + 1]);
            }
            mx = fmaxf(mx, __shfl_xor_sync(0xffffffffu, mx, 1));
            mx = fmaxf(mx, __shfl_xor_sync(0xffffffffu, mx, 2));
            float mnew = fmaxf(mrow[r], mx);
            float scale = __expf(mrow[r] - mnew);
            mrow[r] = mnew;
            float ps = 0.0f;
#pragma unroll
            for (int jn = 0; jn < 8; jn++) {
                float p0 = __expf(sacc[jn][2 * r] - mnew);
                float p1 = __expf(sacc[jn][2 * r + 1] - mnew);
                sacc[jn][2 * r] = p0;
                sacc[jn][2 * r + 1] = p1;
                ps += p0 + p1;
                oacc[jn][2 * r] *= scale;
                oacc[jn][2 * r + 1] *= scale;
            }
            lrow[r] = lrow[r] * scale + ps;
        }

#pragma unroll
        for (int kt = 0; kt < 8; kt++) {
            float x0 = __shfl_sync(0xffffffffu, sacc[kt][0], src1);
            float x1 = __shfl_sync(0xffffffffu, sacc[kt][1], src1);
            float y0 = __shfl_sync(0xffffffffu, sacc[kt][2], src1);
            float y1 = __shfl_sync(0xffffffffu, sacc[kt][3], src1);
            float u0 = __shfl_sync(0xffffffffu, sacc[kt][0], src2);
            float u1 = __shfl_sync(0xffffffffu, sacc[kt][1], src2);
            float v0 = __shfl_sync(0xffffffffu, sacc[kt][2], src2);
            float v1 = __shfl_sync(0xffffffffu, sacc[kt][3], src2);
            uint32_t a0 = f2tf((qd & 1) ? x1 : x0);
            uint32_t a1 = f2tf((qd & 1) ? y1 : y0);
            uint32_t a2 = f2tf((qd & 1) ? u1 : u0);
            uint32_t a3 = f2tf((qd & 1) ? v1 : v0);
            const int k = ch * 64 + 8 * kt;
#pragma unroll
            for (int jn = 0; jn < 8; jn++) {
                int n = 8 * jn + grp;
                uint32_t b0 = VtU[n * VT_STRIDE + k + qd];
                uint32_t b1 = VtU[n * VT_STRIDE + k + qd + 4];
                mma_tf32(oacc[jn][0], oacc[jn][1], oacc[jn][2], oacc[jn][3],
                         a0, a1, a2, a3, b0, b1);
            }
        }
    }

    float inv[2];
#pragma unroll
    for (int r = 0; r < 2; r++) {
        float lr = lrow[r];
        lr += __shfl_xor_sync(0xffffffffu, lr, 1);
        lr += __shfl_xor_sync(0xffffffffu, lr, 2);
        inv[r] = 1.0f / lr;
    }
    float* o0 = g_O + base + (size_t)(m0 + grp) * DIM;
    float* o1 = g_O + base + (size_t)(m0 + grp + 8) * DIM;
#pragma unroll
    for (int jn = 0; jn < 8; jn++) {
        int col = 8 * jn + 2 * qd;
        *(float2*)&o0[col] = make_float2(oacc[jn][0] * inv[0], oacc[jn][1] * inv[0]);
        *(float2*)&o1[col] = make_float2(oacc[jn][2] * inv[1], oacc[jn][3] * inv[1]);
    }
}

// ---------------------------------------------------------------------------
// Kernel 3: output projection + bias, fp16 m16n8k16, same skeleton.
// B = Wo is [n][k] row-major: float4 staging (no transpose). grid: (4, 48)
// ---------------------------------------------------------------------------
__global__ __launch_bounds__(256)
void proj_tc_kernel(const float* __restrict__ Wo,
                    const float* __restrict__ bo,
                    float* __restrict__ out)
{
    __shared__ __align__(16) uint32_t smem[2 * STG_U];

    const int nt = blockIdx.x;
    const int mt = blockIdx.y;

    const int tid  = threadIdx.x;
    const int wid  = tid >> 5;
    const int lane = tid & 31;
    const int wm   = (wid >> 2) * 64;
    const int wn   = (wid & 3) * 32;
    const int grp  = lane >> 2;
    const int qd   = lane & 3;

    const int arow = tid >> 3;   // 0..31
    const int ac   = tid & 7;

    float acc[4][4][4];
#pragma unroll
    for (int i = 0; i < 4; i++)
#pragma unroll
        for (int jn = 0; jn < 4; jn++)
#pragma unroll
            for (int c = 0; c < 4; c++)
                acc[i][jn][c] = 0.0f;

    float pa[16];
    float pb[16];

    auto loadA = [&](int k0) {
#pragma unroll
        for (int l = 0; l < 4; l++) {
            int row = arow + l * 32;
            float4 v = *(const float4*)(g_O +
                ((size_t)(mt * 128 + row)) * DIM + k0 + ac * 4);
            pa[l * 4 + 0] = v.x; pa[l * 4 + 1] = v.y;
            pa[l * 4 + 2] = v.z; pa[l * 4 + 3] = v.w;
        }
#pragma unroll
        for (int l = 0; l < 4; l++) {
            int n = arow + l * 32;
            float4 v = *(const float4*)(Wo +
                (size_t)(nt * 128 + n) * DIM + k0 + ac * 4);
            pb[l * 4 + 0] = v.x; pb[l * 4 + 1] = v.y;
            pb[l * 4 + 2] = v.z; pb[l * 4 + 3] = v.w;
        }
    };
    auto storeS = [&](uint32_t* Ab, uint32_t* Bb) {
#pragma unroll
        for (int l = 0; l < 4; l++) {
            int row = arow + l * 32;
            uint32_t* d = &Ab[row * SAU + ac * 2];
            d[0] = pkh2(pa[l * 4 + 0], pa[l * 4 + 1]);
            d[1] = pkh2(pa[l * 4 + 2], pa[l * 4 + 3]);
        }
#pragma unroll
        for (int l = 0; l < 4; l++) {
            int n = arow + l * 32;
            uint32_t* d = &Bb[n * SAU + ac * 2];
            d[0] = pkh2(pb[l * 4 + 0], pb[l * 4 + 1]);
            d[1] = pkh2(pb[l * 4 + 2], pb[l * 4 + 3]);
        }
    };

    loadA(0);
    storeS(smem, smem + ABUF_U);
    __syncthreads();

    int buf = 0;
    for (int kb = 0; kb < DIM / 32; kb++) {
        if (kb + 1 < DIM / 32) loadA((kb + 1) * 32);

        const uint32_t* Asu = smem + buf * STG_U;
        const uint32_t* Bsu = Asu + ABUF_U;

#pragma unroll
        for (int kk = 0; kk < 2; kk++) {
            const int kp = kk * 8;
            uint32_t a[4][4];
#pragma unroll
            for (int i = 0; i < 4; i++) {
                int r0 = wm + 16 * i + grp;
                a[i][0] = Asu[r0 * SAU + kp + qd];
                a[i][1] = Asu[(r0 + 8) * SAU + kp + qd];
                a[i][2] = Asu[r0 * SAU + kp + qd + 4];
                a[i][3] = Asu[(r0 + 8) * SAU + kp + qd + 4];
            }
            uint32_t b[4][2];
#pragma unroll
            for (int jn = 0; jn < 4; jn++) {
                int n = wn + 8 * jn + grp;
                b[jn][0] = Bsu[n * SAU + kp + qd];
                b[jn][1] = Bsu[n * SAU + kp + qd + 4];
            }
#pragma unroll
            for (int i = 0; i < 4; i++)
#pragma unroll
                for (int jn = 0; jn < 4; jn++)
                    mma_f16(acc[i][jn][0], acc[i][jn][1], acc[i][jn][2], acc[i][jn][3],
                            a[i][0], a[i][1], a[i][2], a[i][3],
                            b[jn][0], b[jn][1]);
        }
        __syncthreads();
        if (kb + 1 < DIM / 32) {
            uint32_t* Ab2 = smem + (buf ^ 1) * STG_U;
            storeS(Ab2, Ab2 + ABUF_U);
        }
        __syncthreads();
        buf ^= 1;
    }

    // Epilogue with bias, remap r=(b*NJ+j)*T+t -> [b][t][j][e]
#pragma unroll
    for (int i = 0; i < 4; i++) {
        int r = mt * 128 + wm + 16 * i + grp;
        int b = r / (NJ * SEQT);
        int rem = r - b * (NJ * SEQT);
        int jj = rem >> 8;
        int t  = rem & (SEQT - 1);
        size_t base0 = (((size_t)(b * SEQT + t) * NJ) + jj) * DIM + nt * 128 + wn;
        size_t base1 = base0 + (size_t)8 * NJ * DIM;  // t+8 (same b, jj)
#pragma unroll
        for (int jn = 0; jn < 4; jn++) {
            int col = 8 * jn + 2 * qd;
            float2 bb = *(const float2*)(bo + nt * 128 + wn + col);
            *(float2*)&out[base0 + col] = make_float2(acc[i][jn][0] + bb.x,
                                                      acc[i][jn][1] + bb.y);
            *(float2*)&out[base1 + col] = make_float2(acc[i][jn][2] + bb.x,
                                                      acc[i][jn][3] + bb.y);
        }
    }
}

// ---------------------------------------------------------------------------
extern "C" void kernel_launch(void* const* d_in, const int* in_sizes, int n_in,
                              void* d_out, int out_size)
{
    const float* x  = (const float*)d_in[0];
    const float* Wq = (const float*)d_in[1];
    const float* Wk = (const float*)d_in[2];
    const float* Wv = (const float*)d_in[3];
    const float* Wo = (const float*)d_in[4];
    const float* bo = (const float*)d_in[5];
    float* out = (float*)d_out;

    // 1) QKV projection (fp16 tensor cores)
    dim3 g1(DIM / 128, (BSZ * SEQT) / 128, 3 * NJ);   // (4, 16, 72)
    qkv_tc_kernel<<<g1, 256>>>(x, Wq, Wk, Wv);

    // 2) attention (tf32 tensor cores)
    cudaFuncSetAttribute(attn_tc_kernel,
                         cudaFuncAttributeMaxDynamicSharedMemorySize, ATT_SMEM);
    attn_tc_kernel<<<BSZ * NJ * NH, 512, ATT_SMEM>>>();

    // 3) output projection + bias (fp16 tensor cores)
    dim3 g3(DIM / 128, (BSZ * SEQT * NJ) / 128);      // (4, 48)
    proj_tc_kernel<<<g3, 256>>>(Wo, bo, out);
}

// round 9
// speedup vs baseline: 1.9516x; 1.3032x over previous
#include <cuda_runtime.h>
#include <cuda_fp16.h>
#include <cstdint>

// Problem constants
#define BSZ 8
#define SEQT 256
#define NJ 24
#define DIM 512
#define NH 8
#define HD 64

#define QKV_ELEMS (BSZ * NJ * SEQT * DIM)  // 25,165,824
#define W_ELEMS   (NJ * DIM * DIM)         // 6,291,456

// fp32 scratch for attention inputs (layout [b][j][t][e])
__device__ float g_Q[QKV_ELEMS];
__device__ float g_K[QKV_ELEMS];
__device__ float g_V[QKV_ELEMS];

// fp16 pre-converted operands
__device__ __half g_Xh[QKV_ELEMS];       // x, same layout [b][t][j][d]
__device__ __half g_Whq[W_ELEMS];        // W transposed: [j][n][k]
__device__ __half g_Whk[W_ELEMS];
__device__ __half g_Whv[W_ELEMS];
__device__ __half g_Woh[DIM * DIM];      // Wo already [n][k]
__device__ __half g_Oh[QKV_ELEMS];       // attention output (half), [b][j][t][e]

__device__ __forceinline__ float to_tf32(float x) {
    uint32_t r;
    asm("cvt.rna.tf32.f32 %0, %1;" : "=r"(r) : "f"(x));
    return __uint_as_float(r);
}
__device__ __forceinline__ uint32_t f2tf(float x) {
    uint32_t r;
    asm("cvt.rna.tf32.f32 %0, %1;" : "=r"(r) : "f"(x));
    return r;
}
__device__ __forceinline__ uint32_t pkh2(float x, float y) {
    __half2 h = __float22half2_rn(make_float2(x, y));
    return *(uint32_t*)&h;
}

__device__ __forceinline__ void mma_tf32(
    float& c0, float& c1, float& c2, float& c3,
    uint32_t a0, uint32_t a1, uint32_t a2, uint32_t a3,
    uint32_t b0, uint32_t b1)
{
    asm volatile(
        "mma.sync.aligned.m16n8k8.row.col.f32.tf32.tf32.f32 "
        "{%0,%1,%2,%3}, {%4,%5,%6,%7}, {%8,%9}, {%0,%1,%2,%3};\n"
        : "+f"(c0), "+f"(c1), "+f"(c2), "+f"(c3)
        : "r"(a0), "r"(a1), "r"(a2), "r"(a3), "r"(b0), "r"(b1));
}
__device__ __forceinline__ void mma_f16(
    float& c0, float& c1, float& c2, float& c3,
    uint32_t a0, uint32_t a1, uint32_t a2, uint32_t a3,
    uint32_t b0, uint32_t b1)
{
    asm volatile(
        "mma.sync.aligned.m16n8k16.row.col.f32.f16.f16.f32 "
        "{%0,%1,%2,%3}, {%4,%5,%6,%7}, {%8,%9}, {%0,%1,%2,%3};\n"
        : "+f"(c0), "+f"(c1), "+f"(c2), "+f"(c3)
        : "r"(a0), "r"(a1), "r"(a2), "r"(a3), "r"(b0), "r"(b1));
}

__device__ __forceinline__ void cpasync16(uint32_t dst, const void* src) {
    asm volatile("cp.async.cg.shared.global [%0], [%1], 16;\n"
                 :: "r"(dst), "l"(src));
}
#define CP_COMMIT() asm volatile("cp.async.commit_group;\n" ::: "memory")
#define CP_WAIT(N)  asm volatile("cp.async.wait_group %0;\n" :: "n"(N) : "memory")

// fp16 GEMM smem: u32(=half2) rows, stride 20 u32 (16 data + 4 pad)
// Fragment LDS bank = (20*grp + qd + kp) mod 32 -> conflict-free (R8-verified)
#define SAU 20
#define ABUF_U (128 * SAU)          // 2560 u32
#define STG_U  (2 * ABUF_U)         // 5120 u32 = 20480 B per stage

// ---------------------------------------------------------------------------
// Pre-pass kernels
// ---------------------------------------------------------------------------
__global__ __launch_bounds__(256)
void cvt_half_kernel(const float4* __restrict__ in, uint2* __restrict__ out, int n4)
{
    int i = blockIdx.x * blockDim.x + threadIdx.x;
    if (i < n4) {
        float4 v = in[i];
        out[i] = make_uint2(pkh2(v.x, v.y), pkh2(v.z, v.w));
    }
}

// Transpose W[j][k][n] (f32) -> Wh[j][n][k] (half). grid (16,16,72), block (32,8)
__global__ __launch_bounds__(256)
void cvt_wt_kernel(const float* __restrict__ Wq,
                   const float* __restrict__ Wk,
                   const float* __restrict__ Wv)
{
    __shared__ float tile[32][33];
    const int z = blockIdx.z;
    const int j = z % NJ;
    const int p = z / NJ;
    const float* W = (p == 0) ? Wq : ((p == 1) ? Wk : Wv);
    __half* Wh     = (p == 0) ? g_Whq : ((p == 1) ? g_Whk : g_Whv);

    const int n0 = blockIdx.x * 32;
    const int k0 = blockIdx.y * 32;
    const int tx = threadIdx.x;
    const int ty = threadIdx.y;
    const size_t base = (size_t)j * DIM * DIM;

#pragma unroll
    for (int i = 0; i < 4; i++)
        tile[ty + 8 * i][tx] = W[base + (size_t)(k0 + ty + 8 * i) * DIM + n0 + tx];
    __syncthreads();
#pragma unroll
    for (int i = 0; i < 4; i++)
        Wh[base + (size_t)(n0 + ty + 8 * i) * DIM + k0 + tx] =
            __float2half(tile[tx][ty + 8 * i]);
}

// ---------------------------------------------------------------------------
// Kernel 1: per-joint Q/K/V projection, fp16 m16n8k16 + cp.async, 2 CTAs/SM.
// Block 128x128, BK=32, 256 threads (8 warps, 2Mx4N, warp 64x32).
// grid: (4, 16, 72)
// ---------------------------------------------------------------------------
__global__ __launch_bounds__(256, 2)
void qkv_tc_kernel()
{
    __shared__ __align__(16) uint32_t smem[2 * STG_U];
    const uint32_t sbase = (uint32_t)__cvta_generic_to_shared(smem);

    const int nt = blockIdx.x;
    const int mt = blockIdx.y;
    const int z  = blockIdx.z;
    const int j  = z % NJ;
    const int p  = z / NJ;

    const __half* Wh = (p == 0) ? g_Whq : ((p == 1) ? g_Whk : g_Whv);
    float* outp      = (p == 0) ? g_Q : ((p == 1) ? g_K : g_V);

    const int tid  = threadIdx.x;
    const int wid  = tid >> 5;
    const int lane = tid & 31;
    const int wm   = (wid >> 2) * 64;
    const int wn   = (wid & 3) * 32;
    const int grp  = lane >> 2;
    const int qd   = lane & 3;

    const size_t wbase = (size_t)j * DIM * DIM + (size_t)nt * 128 * DIM;

    float acc[4][4][4];
#pragma unroll
    for (int i = 0; i < 4; i++)
#pragma unroll
        for (int jn = 0; jn < 4; jn++)
#pragma unroll
            for (int c = 0; c < 4; c++)
                acc[i][jn][c] = 0.0f;

    auto stage = [&](int kb, int bf) {
        uint32_t ab = sbase + bf * (STG_U * 4);
        uint32_t bb = ab + ABUF_U * 4;
#pragma unroll
        for (int l = 0; l < 2; l++) {
            int c   = tid + l * 256;
            int row = c >> 2;
            int cc  = c & 3;
            cpasync16(ab + row * (SAU * 4) + cc * 16,
                      g_Xh + ((size_t)(mt * 128 + row) * NJ + j) * DIM + kb * 32 + cc * 8);
            cpasync16(bb + row * (SAU * 4) + cc * 16,
                      Wh + wbase + (size_t)row * DIM + kb * 32 + cc * 8);
        }
    };

    stage(0, 0);
    CP_COMMIT();

    int buf = 0;
    for (int kb = 0; kb < DIM / 32; kb++) {
        if (kb + 1 < DIM / 32) {
            stage(kb + 1, buf ^ 1);
            CP_COMMIT();
            CP_WAIT(1);
        } else {
            CP_WAIT(0);
        }
        __syncthreads();

        const uint32_t* Asu = smem + buf * STG_U;
        const uint32_t* Bsu = Asu + ABUF_U;

#pragma unroll
        for (int kk = 0; kk < 2; kk++) {
            const int kp = kk * 8;
            uint32_t a[4][4];
#pragma unroll
            for (int i = 0; i < 4; i++) {
                int r0 = wm + 16 * i + grp;
                a[i][0] = Asu[r0 * SAU + kp + qd];
                a[i][1] = Asu[(r0 + 8) * SAU + kp + qd];
                a[i][2] = Asu[r0 * SAU + kp + qd + 4];
                a[i][3] = Asu[(r0 + 8) * SAU + kp + qd + 4];
            }
            uint32_t b[4][2];
#pragma unroll
            for (int jn = 0; jn < 4; jn++) {
                int n = wn + 8 * jn + grp;
                b[jn][0] = Bsu[n * SAU + kp + qd];
                b[jn][1] = Bsu[n * SAU + kp + qd + 4];
            }
#pragma unroll
            for (int i = 0; i < 4; i++)
#pragma unroll
                for (int jn = 0; jn < 4; jn++)
                    mma_f16(acc[i][jn][0], acc[i][jn][1], acc[i][jn][2], acc[i][jn][3],
                            a[i][0], a[i][1], a[i][2], a[i][3],
                            b[jn][0], b[jn][1]);
        }
        __syncthreads();
        buf ^= 1;
    }

    // Epilogue: store fp32 to [b][j][t][e] for attention
#pragma unroll
    for (int i = 0; i < 4; i++) {
        int m = mt * 128 + wm + 16 * i + grp;
        int b = m >> 8;
        int t = m & (SEQT - 1);
        size_t base0 = (((size_t)(b * NJ + j) * SEQT) + t) * DIM + nt * 128 + wn;
        size_t base1 = base0 + (size_t)8 * DIM;
#pragma unroll
        for (int jn = 0; jn < 4; jn++) {
            int col = 8 * jn + 2 * qd;
            *(float2*)&outp[base0 + col] = make_float2(acc[i][jn][0], acc[i][jn][1]);
            *(float2*)&outp[base1 + col] = make_float2(acc[i][jn][2], acc[i][jn][3]);
        }
    }
}

// ---------------------------------------------------------------------------
// Kernel 2: flash-style tensor-core attention (R5 math; writes half g_Oh).
// ---------------------------------------------------------------------------
#define KS_STRIDE 68
#define VT_STRIDE 260
#define ATT_SMEM_FLOATS (2 * SEQT * KS_STRIDE + HD * VT_STRIDE)  // 51456
#define ATT_SMEM (ATT_SMEM_FLOATS * 4)                           // 205824 B

__global__ __launch_bounds__(512)
void attn_tc_kernel()
{
    extern __shared__ float sm[];
    float* Qs = sm;
    float* Ks = sm + SEQT * KS_STRIDE;
    float* Vt = sm + 2 * SEQT * KS_STRIDE;

    const int bjh = blockIdx.x;
    const int h   = bjh & (NH - 1);
    const int bj  = bjh >> 3;
    const int tid  = threadIdx.x;
    const int wid  = tid >> 5;
    const int lane = tid & 31;
    const int grp  = lane >> 2;
    const int qd   = lane & 3;
    const int m0   = wid * 16;

    const size_t base = (size_t)bj * SEQT * DIM + h * HD;
    const float* qg = g_Q + base;
    const float* kg = g_K + base;
    const float* vg = g_V + base;

#pragma unroll
    for (int l = 0; l < 8; l++) {
        int idx = tid + l * 512;
        int s  = idx >> 4;
        int dq = (idx & 15) * 4;
        float4 q = *(const float4*)(qg + (size_t)s * DIM + dq);
        float* dst = &Qs[s * KS_STRIDE + dq];
        dst[0] = to_tf32(q.x * 0.125f); dst[1] = to_tf32(q.y * 0.125f);
        dst[2] = to_tf32(q.z * 0.125f); dst[3] = to_tf32(q.w * 0.125f);
        float4 k = *(const float4*)(kg + (size_t)s * DIM + dq);
        float* dk = &Ks[s * KS_STRIDE + dq];
        dk[0] = to_tf32(k.x); dk[1] = to_tf32(k.y);
        dk[2] = to_tf32(k.z); dk[3] = to_tf32(k.w);
    }
#pragma unroll
    for (int l = 0; l < 8; l++) {
        int idx = tid + l * 512;
        int d  = idx & 63;
        int s0 = (idx >> 6) * 4;
        float4 v;
        v.x = to_tf32(vg[(size_t)(s0 + 0) * DIM + d]);
        v.y = to_tf32(vg[(size_t)(s0 + 1) * DIM + d]);
        v.z = to_tf32(vg[(size_t)(s0 + 2) * DIM + d]);
        v.w = to_tf32(vg[(size_t)(s0 + 3) * DIM + d]);
        *(float4*)&Vt[d * VT_STRIDE + s0] = v;
    }
    __syncthreads();

    const uint32_t* QsU = (const uint32_t*)Qs;
    const uint32_t* KsU = (const uint32_t*)Ks;
    const uint32_t* VtU = (const uint32_t*)Vt;

    float oacc[8][4];
#pragma unroll
    for (int jn = 0; jn < 8; jn++)
#pragma unroll
        for (int c = 0; c < 4; c++) oacc[jn][c] = 0.0f;
    float mrow[2] = { -1e30f, -1e30f };
    float lrow[2] = { 0.0f, 0.0f };

    const int src1 = (lane & ~3) | (qd >> 1);
    const int src2 = src1 + 2;

    for (int ch = 0; ch < 4; ch++) {
        float sacc[8][4];
#pragma unroll
        for (int jn = 0; jn < 8; jn++)
#pragma unroll
            for (int c = 0; c < 4; c++) sacc[jn][c] = 0.0f;

#pragma unroll
        for (int kt = 0; kt < 8; kt++) {
            const int k = 8 * kt;
            int r0 = m0 + grp;
            uint32_t a0 = QsU[r0 * KS_STRIDE + k + qd];
            uint32_t a1 = QsU[(r0 + 8) * KS_STRIDE + k + qd];
            uint32_t a2 = QsU[r0 * KS_STRIDE + k + qd + 4];
            uint32_t a3 = QsU[(r0 + 8) * KS_STRIDE + k + qd + 4];
            uint32_t b[8][2];
#pragma unroll
            for (int jn = 0; jn < 8; jn++) {
                int n = ch * 64 + 8 * jn + grp;
                b[jn][0] = KsU[n * KS_STRIDE + k + qd];
                b[jn][1] = KsU[n * KS_STRIDE + k + qd + 4];
            }
#pragma unroll
            for (int jn = 0; jn < 8; jn++)
                mma_tf32(sacc[jn][0], sacc[jn][1], sacc[jn][2], sacc[jn][3],
                         a0, a1, a2, a3, b[jn][0], b[jn][1]);
        }

#pragma unroll
        for (int r = 0; r < 2; r++) {
            float mx = -1e30f;
#pragma unroll
            for (int jn = 0; jn < 8; jn++) {
                mx = fmaxf(mx, sacc[jn][2 * r]);
                mx = fmaxf(mx, sacc[jn][2 * r + 1]);
            }
            mx = fmaxf(mx, __shfl_xor_sync(0xffffffffu, mx, 1));
            mx = fmaxf(mx, __shfl_xor_sync(0xffffffffu, mx, 2));
            float mnew = fmaxf(mrow[r], mx);
            float scale = __expf(mrow[r] - mnew);
            mrow[r] = mnew;
            float ps = 0.0f;
#pragma unroll
            for (int jn = 0; jn < 8; jn++) {
                float p0 = __expf(sacc[jn][2 * r] - mnew);
                float p1 = __expf(sacc[jn][2 * r + 1] - mnew);
                sacc[jn][2 * r] = p0;
                sacc[jn][2 * r + 1] = p1;
                ps += p0 + p1;
                oacc[jn][2 * r] *= scale;
                oacc[jn][2 * r + 1] *= scale;
            }
            lrow[r] = lrow[r] * scale + ps;
        }

#pragma unroll
        for (int kt = 0; kt < 8; kt++) {
            float x0 = __shfl_sync(0xffffffffu, sacc[kt][0], src1);
            float x1 = __shfl_sync(0xffffffffu, sacc[kt][1], src1);
            float y0 = __shfl_sync(0xffffffffu, sacc[kt][2], src1);
            float y1 = __shfl_sync(0xffffffffu, sacc[kt][3], src1);
            float u0 = __shfl_sync(0xffffffffu, sacc[kt][0], src2);
            float u1 = __shfl_sync(0xffffffffu, sacc[kt][1], src2);
            float v0 = __shfl_sync(0xffffffffu, sacc[kt][2], src2);
            float v1 = __shfl_sync(0xffffffffu, sacc[kt][3], src2);
            uint32_t a0 = f2tf((qd & 1) ? x1 : x0);
            uint32_t a1 = f2tf((qd & 1) ? y1 : y0);
            uint32_t a2 = f2tf((qd & 1) ? u1 : u0);
            uint32_t a3 = f2tf((qd & 1) ? v1 : v0);
            const int k = ch * 64 + 8 * kt;
#pragma unroll
            for (int jn = 0; jn < 8; jn++) {
                int n = 8 * jn + grp;
                uint32_t b0 = VtU[n * VT_STRIDE + k + qd];
                uint32_t b1 = VtU[n * VT_STRIDE + k + qd + 4];
                mma_tf32(oacc[jn][0], oacc[jn][1], oacc[jn][2], oacc[jn][3],
                         a0, a1, a2, a3, b0, b1);
            }
        }
    }

    float inv[2];
#pragma unroll
    for (int r = 0; r < 2; r++) {
        float lr = lrow[r];
        lr += __shfl_xor_sync(0xffffffffu, lr, 1);
        lr += __shfl_xor_sync(0xffffffffu, lr, 2);
        inv[r] = 1.0f / lr;
    }
    // store half (proj consumes via cp.async)
    __half* o0 = g_Oh + base + (size_t)(m0 + grp) * DIM;
    __half* o1 = g_Oh + base + (size_t)(m0 + grp + 8) * DIM;
#pragma unroll
    for (int jn = 0; jn < 8; jn++) {
        int col = 8 * jn + 2 * qd;
        *(uint32_t*)&o0[col] = pkh2(oacc[jn][0] * inv[0], oacc[jn][1] * inv[0]);
        *(uint32_t*)&o1[col] = pkh2(oacc[jn][2] * inv[1], oacc[jn][3] * inv[1]);
    }
}

// ---------------------------------------------------------------------------
// Kernel 3: output projection + bias, fp16 + cp.async, 2 CTAs/SM. grid (4,48)
// ---------------------------------------------------------------------------
__global__ __launch_bounds__(256, 2)
void proj_tc_kernel(const float* __restrict__ bo,
                    float* __restrict__ out)
{
    __shared__ __align__(16) uint32_t smem[2 * STG_U];
    const uint32_t sbase = (uint32_t)__cvta_generic_to_shared(smem);

    const int nt = blockIdx.x;
    const int mt = blockIdx.y;

    const int tid  = threadIdx.x;
    const int wid  = tid >> 5;
    const int lane = tid & 31;
    const int wm   = (wid >> 2) * 64;
    const int wn   = (wid & 3) * 32;
    const int grp  = lane >> 2;
    const int qd   = lane & 3;

    float acc[4][4][4];
#pragma unroll
    for (int i = 0; i < 4; i++)
#pragma unroll
        for (int jn = 0; jn < 4; jn++)
#pragma unroll
            for (int c = 0; c < 4; c++)
                acc[i][jn][c] = 0.0f;

    auto stage = [&](int kb, int bf) {
        uint32_t ab = sbase + bf * (STG_U * 4);
        uint32_t bb = ab + ABUF_U * 4;
#pragma unroll
        for (int l = 0; l < 2; l++) {
            int c   = tid + l * 256;
            int row = c >> 2;
            int cc  = c & 3;
            cpasync16(ab + row * (SAU * 4) + cc * 16,
                      g_Oh + (size_t)(mt * 128 + row) * DIM + kb * 32 + cc * 8);
            cpasync16(bb + row * (SAU * 4) + cc * 16,
                      g_Woh + (size_t)(nt * 128 + row) * DIM + kb * 32 + cc * 8);
        }
    };

    stage(0, 0);
    CP_COMMIT();

    int buf = 0;
    for (int kb = 0; kb < DIM / 32; kb++) {
        if (kb + 1 < DIM / 32) {
            stage(kb + 1, buf ^ 1);
            CP_COMMIT();
            CP_WAIT(1);
        } else {
            CP_WAIT(0);
        }
        __syncthreads();

        const uint32_t* Asu = smem + buf * STG_U;
        const uint32_t* Bsu = Asu + ABUF_U;

#pragma unroll
        for (int kk = 0; kk < 2; kk++) {
            const int kp = kk * 8;
            uint32_t a[4][4];
#pragma unroll
            for (int i = 0; i < 4; i++) {
                int r0 = wm + 16 * i + grp;
                a[i][0] = Asu[r0 * SAU + kp + qd];
                a[i][1] = Asu[(r0 + 8) * SAU + kp + qd];
                a[i][2] = Asu[r0 * SAU + kp + qd + 4];
                a[i][3] = Asu[(r0 + 8) * SAU + kp + qd + 4];
            }
            uint32_t b[4][2];
#pragma unroll
            for (int jn = 0; jn < 4; jn++) {
                int n = wn + 8 * jn + grp;
                b[jn][0] = Bsu[n * SAU + kp + qd];
                b[jn][1] = Bsu[n * SAU + kp + qd + 4];
            }
#pragma unroll
            for (int i = 0; i < 4; i++)
#pragma unroll
                for (int jn = 0; jn < 4; jn++)
                    mma_f16(acc[i][jn][0], acc[i][jn][1], acc[i][jn][2], acc[i][jn][3],
                            a[i][0], a[i][1], a[i][2], a[i][3],
                            b[jn][0], b[jn][1]);
        }
        __syncthreads();
        buf ^= 1;
    }

    // Epilogue with bias, remap r=(b*NJ+j)*T+t -> [b][t][j][e]
#pragma unroll
    for (int i = 0; i < 4; i++) {
        int r = mt * 128 + wm + 16 * i + grp;
        int b = r / (NJ * SEQT);
        int rem = r - b * (NJ * SEQT);
        int jj = rem >> 8;
        int t  = rem & (SEQT - 1);
        size_t base0 = (((size_t)(b * SEQT + t) * NJ) + jj) * DIM + nt * 128 + wn;
        size_t base1 = base0 + (size_t)8 * NJ * DIM;
#pragma unroll
        for (int jn = 0; jn < 4; jn++) {
            int col = 8 * jn + 2 * qd;
            float2 bb = *(const float2*)(bo + nt * 128 + wn + col);
            *(float2*)&out[base0 + col] = make_float2(acc[i][jn][0] + bb.x,
                                                      acc[i][jn][1] + bb.y);
            *(float2*)&out[base1 + col] = make_float2(acc[i][jn][2] + bb.x,
                                                      acc[i][jn][3] + bb.y);
        }
    }
}

// ---------------------------------------------------------------------------
extern "C" void kernel_launch(void* const* d_in, const int* in_sizes, int n_in,
                              void* d_out, int out_size)
{
    const float* x  = (const float*)d_in[0];
    const float* Wq = (const float*)d_in[1];
    const float* Wk = (const float*)d_in[2];
    const float* Wv = (const float*)d_in[3];
    const float* Wo = (const float*)d_in[4];
    const float* bo = (const float*)d_in[5];
    float* out = (float*)d_out;

    void* xh;  cudaGetSymbolAddress(&xh,  g_Xh);
    void* woh; cudaGetSymbolAddress(&woh, g_Woh);

    // 0) pre-convert to half (x, Wo: same layout; Wq/k/v: transposed)
    cvt_half_kernel<<<(QKV_ELEMS / 4 + 255) / 256, 256>>>(
        (const float4*)x, (uint2*)xh, QKV_ELEMS / 4);
    cvt_wt_kernel<<<dim3(16, 16, 72), dim3(32, 8)>>>(Wq, Wk, Wv);
    cvt_half_kernel<<<(DIM * DIM / 4 + 255) / 256, 256>>>(
        (const float4*)Wo, (uint2*)woh, DIM * DIM / 4);

    // 1) QKV projection (fp16 tensor cores + cp.async, 2 CTAs/SM)
    dim3 g1(DIM / 128, (BSZ * SEQT) / 128, 3 * NJ);   // (4, 16, 72)
    qkv_tc_kernel<<<g1, 256>>>();

    // 2) attention (tf32 tensor cores)
    cudaFuncSetAttribute(attn_tc_kernel,
                         cudaFuncAttributeMaxDynamicSharedMemorySize, ATT_SMEM);
    attn_tc_kernel<<<BSZ * NJ * NH, 512, ATT_SMEM>>>();

    // 3) output projection + bias (fp16 + cp.async, 2 CTAs/SM)
    dim3 g3(DIM / 128, (BSZ * SEQT * NJ) / 128);      // (4, 48)
    proj_tc_kernel<<<g3, 256>>>(bo, out);
}

// round 10
// speedup vs baseline: 2.3880x; 1.2236x over previous
#include <cuda_runtime.h>
#include <cuda_fp16.h>
#include <cstdint>

// Problem constants
#define BSZ 8
#define SEQT 256
#define NJ 24
#define DIM 512
#define NH 8
#define HD 64

#define QKV_ELEMS (BSZ * NJ * SEQT * DIM)  // 25,165,824
#define W_ELEMS   (NJ * DIM * DIM)         // 6,291,456

// fp16 operands / intermediates
__device__ __half g_Xh[QKV_ELEMS];       // x, layout [b][t][j][d]
__device__ __half g_Whq[W_ELEMS];        // W transposed: [j][n][k]
__device__ __half g_Whk[W_ELEMS];
__device__ __half g_Whv[W_ELEMS];
__device__ __half g_Woh[DIM * DIM];      // Wo [n][k]
__device__ __half g_Qh[QKV_ELEMS];       // Q pre-scaled by 0.125, [b][j][t][e]
__device__ __half g_Kh[QKV_ELEMS];       // K, [b][j][t][e]
__device__ __half g_Vth[QKV_ELEMS];      // V transposed, [b][j][e][t]
__device__ __half g_Oh[QKV_ELEMS];       // attention out, [b][j][t][e]

__device__ __forceinline__ uint32_t pkh2(float x, float y) {
    __half2 h = __float22half2_rn(make_float2(x, y));
    return *(uint32_t*)&h;
}

__device__ __forceinline__ void mma_f16(
    float& c0, float& c1, float& c2, float& c3,
    uint32_t a0, uint32_t a1, uint32_t a2, uint32_t a3,
    uint32_t b0, uint32_t b1)
{
    asm volatile(
        "mma.sync.aligned.m16n8k16.row.col.f32.f16.f16.f32 "
        "{%0,%1,%2,%3}, {%4,%5,%6,%7}, {%8,%9}, {%0,%1,%2,%3};\n"
        : "+f"(c0), "+f"(c1), "+f"(c2), "+f"(c3)
        : "r"(a0), "r"(a1), "r"(a2), "r"(a3), "r"(b0), "r"(b1));
}

__device__ __forceinline__ void cpasync16(uint32_t dst, const void* src) {
    asm volatile("cp.async.cg.shared.global [%0], [%1], 16;\n"
                 :: "r"(dst), "l"(src));
}
#define CP_COMMIT() asm volatile("cp.async.commit_group;\n" ::: "memory")
#define CP_WAIT(N)  asm volatile("cp.async.wait_group %0;\n" :: "n"(N) : "memory")

// fp16 GEMM smem: u32(=half2) rows, stride 20 u32 (16 data + 4 pad)
// Fragment LDS bank = (20*grp + qd + kp) mod 32 -> conflict-free (R8/R9-verified)
#define SAU 20
#define ABUF_U (128 * SAU)          // 2560 u32
#define STG_U  (2 * ABUF_U)         // 5120 u32 = 20480 B per stage
#define QKV_SMEM (3 * STG_U * 4)    // 61440 B (3-stage)

// ---------------------------------------------------------------------------
// Pre-pass kernels
// ---------------------------------------------------------------------------
__global__ __launch_bounds__(256)
void cvt_half_kernel(const float4* __restrict__ in, uint2* __restrict__ out, int n4)
{
    int i = blockIdx.x * blockDim.x + threadIdx.x;
    if (i < n4) {
        float4 v = in[i];
        out[i] = make_uint2(pkh2(v.x, v.y), pkh2(v.z, v.w));
    }
}

// Transpose W[j][k][n] (f32) -> Wh[j][n][k] (half). grid (16,16,72), block (32,8)
__global__ __launch_bounds__(256)
void cvt_wt_kernel(const float* __restrict__ Wq,
                   const float* __restrict__ Wk,
                   const float* __restrict__ Wv)
{
    __shared__ float tile[32][33];
    const int z = blockIdx.z;
    const int j = z % NJ;
    const int p = z / NJ;
    const float* W = (p == 0) ? Wq : ((p == 1) ? Wk : Wv);
    __half* Wh     = (p == 0) ? g_Whq : ((p == 1) ? g_Whk : g_Whv);

    const int n0 = blockIdx.x * 32;
    const int k0 = blockIdx.y * 32;
    const int tx = threadIdx.x;
    const int ty = threadIdx.y;
    const size_t base = (size_t)j * DIM * DIM;

#pragma unroll
    for (int i = 0; i < 4; i++)
        tile[ty + 8 * i][tx] = W[base + (size_t)(k0 + ty + 8 * i) * DIM + n0 + tx];
    __syncthreads();
#pragma unroll
    for (int i = 0; i < 4; i++)
        Wh[base + (size_t)(n0 + ty + 8 * i) * DIM + k0 + tx] =
            __float2half(tile[tx][ty + 8 * i]);
}

// ---------------------------------------------------------------------------
// Kernel 1: per-joint Q/K/V projection, fp16 m16n8k16 + 3-stage cp.async.
// Block 128x128, BK=32, 256 threads (8 warps, 2Mx4N, warp 64x32), 2 CTAs/SM.
// Outputs: Q (x0.125) / K half [b][j][t][e]; V half transposed [b][j][e][t].
// grid: (4, 16, 72)
// ---------------------------------------------------------------------------
__global__ __launch_bounds__(256, 2)
void qkv_tc_kernel()
{
    extern __shared__ uint32_t smem[];
    const uint32_t sbase = (uint32_t)__cvta_generic_to_shared(smem);

    const int nt = blockIdx.x;
    const int mt = blockIdx.y;
    const int z  = blockIdx.z;
    const int j  = z % NJ;
    const int p  = z / NJ;

    const __half* Wh = (p == 0) ? g_Whq : ((p == 1) ? g_Whk : g_Whv);

    const int tid  = threadIdx.x;
    const int wid  = tid >> 5;
    const int lane = tid & 31;
    const int wm   = (wid >> 2) * 64;
    const int wn   = (wid & 3) * 32;
    const int grp  = lane >> 2;
    const int qd   = lane & 3;

    const size_t wbase = (size_t)j * DIM * DIM + (size_t)nt * 128 * DIM;

    float acc[4][4][4];
#pragma unroll
    for (int i = 0; i < 4; i++)
#pragma unroll
        for (int jn = 0; jn < 4; jn++)
#pragma unroll
            for (int c = 0; c < 4; c++)
                acc[i][jn][c] = 0.0f;

    auto stage = [&](int kb, int bf) {
        uint32_t ab = sbase + bf * (STG_U * 4);
        uint32_t bb = ab + ABUF_U * 4;
#pragma unroll
        for (int l = 0; l < 2; l++) {
            int c   = tid + l * 256;
            int row = c >> 2;
            int cc  = c & 3;
            cpasync16(ab + row * (SAU * 4) + cc * 16,
                      g_Xh + ((size_t)(mt * 128 + row) * NJ + j) * DIM + kb * 32 + cc * 8);
            cpasync16(bb + row * (SAU * 4) + cc * 16,
                      Wh + wbase + (size_t)row * DIM + kb * 32 + cc * 8);
        }
    };

    stage(0, 0);
    CP_COMMIT();
    stage(1, 1);
    CP_COMMIT();

    for (int kb = 0; kb < DIM / 32; kb++) {
        if (kb < DIM / 32 - 1) { CP_WAIT(1); } else { CP_WAIT(0); }
        __syncthreads();
        if (kb + 2 < DIM / 32) {
            stage(kb + 2, (kb + 2) % 3);
            CP_COMMIT();
        }

        const uint32_t* Asu = smem + (kb % 3) * STG_U;
        const uint32_t* Bsu = Asu + ABUF_U;

#pragma unroll
        for (int kk = 0; kk < 2; kk++) {
            const int kp = kk * 8;
            uint32_t a[4][4];
#pragma unroll
            for (int i = 0; i < 4; i++) {
                int r0 = wm + 16 * i + grp;
                a[i][0] = Asu[r0 * SAU + kp + qd];
                a[i][1] = Asu[(r0 + 8) * SAU + kp + qd];
                a[i][2] = Asu[r0 * SAU + kp + qd + 4];
                a[i][3] = Asu[(r0 + 8) * SAU + kp + qd + 4];
            }
            uint32_t b[4][2];
#pragma unroll
            for (int jn = 0; jn < 4; jn++) {
                int n = wn + 8 * jn + grp;
                b[jn][0] = Bsu[n * SAU + kp + qd];
                b[jn][1] = Bsu[n * SAU + kp + qd + 4];
            }
#pragma unroll
            for (int i = 0; i < 4; i++)
#pragma unroll
                for (int jn = 0; jn < 4; jn++)
                    mma_f16(acc[i][jn][0], acc[i][jn][1], acc[i][jn][2], acc[i][jn][3],
                            a[i][0], a[i][1], a[i][2], a[i][3],
                            b[jn][0], b[jn][1]);
        }
    }

    // Epilogue
    if (p < 2) {
        __half* outh = (p == 0) ? g_Qh : g_Kh;
        const float scl = (p == 0) ? 0.125f : 1.0f;
#pragma unroll
        for (int i = 0; i < 4; i++) {
            int m = mt * 128 + wm + 16 * i + grp;
            int b = m >> 8;
            int t = m & (SEQT - 1);
            size_t r0 = (((size_t)(b * NJ + j) * SEQT) + t) * DIM + nt * 128 + wn;
            size_t r1 = r0 + (size_t)8 * DIM;
#pragma unroll
            for (int jn = 0; jn < 4; jn++) {
                int col = 8 * jn + 2 * qd;
                *(uint32_t*)&outh[r0 + col] = pkh2(acc[i][jn][0] * scl, acc[i][jn][1] * scl);
                *(uint32_t*)&outh[r1 + col] = pkh2(acc[i][jn][2] * scl, acc[i][jn][3] * scl);
            }
        }
    } else {
        // V transposed: [b][j][e][t]
#pragma unroll
        for (int i = 0; i < 4; i++) {
            int m = mt * 128 + wm + 16 * i + grp;
            int b = m >> 8;
            int t = m & (SEQT - 1);
#pragma unroll
            for (int jn = 0; jn < 4; jn++) {
                int e = nt * 128 + wn + 8 * jn + 2 * qd;
                size_t base = ((size_t)(b * NJ + j) * DIM + e) * SEQT + t;
                g_Vth[base]            = __float2half(acc[i][jn][0]);
                g_Vth[base + SEQT]     = __float2half(acc[i][jn][1]);
                g_Vth[base + 8]        = __float2half(acc[i][jn][2]);
                g_Vth[base + SEQT + 8] = __float2half(acc[i][jn][3]);
            }
        }
    }
}

// ---------------------------------------------------------------------------
// Kernel 2: fp16 flash attention. One block per (b,j,h), 512 threads/16 warps,
// warp = 16 q-rows. Q/K/Vt staged via cp.async (no conversion). S and PV on
// m16n8k16; P C-frag -> A-frag by local half2 packing (no shuffles).
// ---------------------------------------------------------------------------
#define AQ_ST 36     // Q/K row stride in u32 (32 data + 4 pad)
#define AV_ST 132    // Vt row stride in u32 (128 data + 4 pad)
#define ATT_U (2 * SEQT * AQ_ST + HD * AV_ST)   // 26880 u32
#define ATT_SMEM (ATT_U * 4)                    // 107520 B

__global__ __launch_bounds__(512)
void attn_tc_kernel()
{
    extern __shared__ uint32_t smu[];
    const uint32_t sbase = (uint32_t)__cvta_generic_to_shared(smu);
    const uint32_t* Qs = smu;
    const uint32_t* Ks = smu + SEQT * AQ_ST;
    const uint32_t* Vt = smu + 2 * SEQT * AQ_ST;

    const int bjh = blockIdx.x;
    const int h   = bjh & (NH - 1);
    const int bj  = bjh >> 3;
    const int tid  = threadIdx.x;
    const int wid  = tid >> 5;
    const int lane = tid & 31;
    const int grp  = lane >> 2;
    const int qd   = lane & 3;
    const int m0   = wid * 16;

    const __half* qg = g_Qh + (size_t)bj * SEQT * DIM + h * HD;
    const __half* kg = g_Kh + (size_t)bj * SEQT * DIM + h * HD;
    const __half* vg = g_Vth + (size_t)bj * DIM * SEQT + (size_t)h * HD * SEQT;

    // Stage Q, K: 256 rows x 8 uint4; Vt: 64 rows x 32 uint4
#pragma unroll
    for (int l = 0; l < 4; l++) {
        int idx = tid + l * 512;
        int row = idx >> 3;
        int q4  = idx & 7;
        cpasync16(sbase + (row * AQ_ST + q4 * 4) * 4, qg + (size_t)row * DIM + q4 * 8);
        cpasync16(sbase + (SEQT * AQ_ST + row * AQ_ST + q4 * 4) * 4,
                  kg + (size_t)row * DIM + q4 * 8);
    }
#pragma unroll
    for (int l = 0; l < 4; l++) {
        int idx = tid + l * 512;
        int d  = idx >> 5;
        int q4 = idx & 31;
        cpasync16(sbase + (2 * SEQT * AQ_ST + d * AV_ST + q4 * 4) * 4,
                  vg + (size_t)d * SEQT + q4 * 8);
    }
    CP_COMMIT();
    CP_WAIT(0);
    __syncthreads();

    float oacc[8][4];
#pragma unroll
    for (int jn = 0; jn < 8; jn++)
#pragma unroll
        for (int c = 0; c < 4; c++) oacc[jn][c] = 0.0f;
    float mrow[2] = { -1e30f, -1e30f };
    float lrow[2] = { 0.0f, 0.0f };

    for (int ch = 0; ch < 4; ch++) {
        // ---- S = Q K^T over this 64-key chunk (Q pre-scaled) ----
        float sacc[8][4];
#pragma unroll
        for (int jn = 0; jn < 8; jn++)
#pragma unroll
            for (int c = 0; c < 4; c++) sacc[jn][c] = 0.0f;

#pragma unroll
        for (int kt = 0; kt < 4; kt++) {
            const int kp = kt * 8;
            int r0 = m0 + grp;
            uint32_t a0 = Qs[r0 * AQ_ST + kp + qd];
            uint32_t a1 = Qs[(r0 + 8) * AQ_ST + kp + qd];
            uint32_t a2 = Qs[r0 * AQ_ST + kp + qd + 4];
            uint32_t a3 = Qs[(r0 + 8) * AQ_ST + kp + qd + 4];
#pragma unroll
            for (int jn = 0; jn < 8; jn++) {
                int n = ch * 64 + 8 * jn + grp;
                uint32_t b0 = Ks[n * AQ_ST + kp + qd];
                uint32_t b1 = Ks[n * AQ_ST + kp + qd + 4];
                mma_f16(sacc[jn][0], sacc[jn][1], sacc[jn][2], sacc[jn][3],
                        a0, a1, a2, a3, b0, b1);
            }
        }

        // ---- online softmax (branchless, per-lane partial l) ----
#pragma unroll
        for (int r = 0; r < 2; r++) {
            float mx = -1e30f;
#pragma unroll
            for (int jn = 0; jn < 8; jn++) {
                mx = fmaxf(mx, sacc[jn][2 * r]);
                mx = fmaxf(mx, sacc[jn][2 * r + 1]);
            }
            mx = fmaxf(mx, __shfl_xor_sync(0xffffffffu, mx, 1));
            mx = fmaxf(mx, __shfl_xor_sync(0xffffffffu, mx, 2));
            float mnew = fmaxf(mrow[r], mx);
            float scale = __expf(mrow[r] - mnew);
            mrow[r] = mnew;
            float ps = 0.0f;
#pragma unroll
            for (int jn = 0; jn < 8; jn++) {
                float p0 = __expf(sacc[jn][2 * r] - mnew);
                float p1 = __expf(sacc[jn][2 * r + 1] - mnew);
                sacc[jn][2 * r] = p0;
                sacc[jn][2 * r + 1] = p1;
                ps += p0 + p1;
                oacc[jn][2 * r] *= scale;
                oacc[jn][2 * r + 1] *= scale;
            }
            lrow[r] = lrow[r] * scale + ps;
        }

        // ---- O += P V : P C-frag -> fp16 A-frag by local packing ----
#pragma unroll
        for (int kt = 0; kt < 4; kt++) {
            uint32_t a0 = pkh2(sacc[2 * kt][0], sacc[2 * kt][1]);
            uint32_t a1 = pkh2(sacc[2 * kt][2], sacc[2 * kt][3]);
            uint32_t a2 = pkh2(sacc[2 * kt + 1][0], sacc[2 * kt + 1][1]);
            uint32_t a3 = pkh2(sacc[2 * kt + 1][2], sacc[2 * kt + 1][3]);
            const int kp = ch * 32 + kt * 8;
#pragma unroll
            for (int jn = 0; jn < 8; jn++) {
                int n = 8 * jn + grp;           // d-dimension
                uint32_t b0 = Vt[n * AV_ST + kp + qd];
                uint32_t b1 = Vt[n * AV_ST + kp + qd + 4];
                mma_f16(oacc[jn][0], oacc[jn][1], oacc[jn][2], oacc[jn][3],
                        a0, a1, a2, a3, b0, b1);
            }
        }
    }

    // ---- finalize: reduce l over quad, normalize, store half ----
    float inv[2];
#pragma unroll
    for (int r = 0; r < 2; r++) {
        float lr = lrow[r];
        lr += __shfl_xor_sync(0xffffffffu, lr, 1);
        lr += __shfl_xor_sync(0xffffffffu, lr, 2);
        inv[r] = 1.0f / lr;
    }
    const size_t obase = (size_t)bj * SEQT * DIM + h * HD;
    __half* o0 = g_Oh + obase + (size_t)(m0 + grp) * DIM;
    __half* o1 = g_Oh + obase + (size_t)(m0 + grp + 8) * DIM;
#pragma unroll
    for (int jn = 0; jn < 8; jn++) {
        int col = 8 * jn + 2 * qd;
        *(uint32_t*)&o0[col] = pkh2(oacc[jn][0] * inv[0], oacc[jn][1] * inv[0]);
        *(uint32_t*)&o1[col] = pkh2(oacc[jn][2] * inv[1], oacc[jn][3] * inv[1]);
    }
}

// ---------------------------------------------------------------------------
// Kernel 3: output projection + bias, fp16 + cp.async, 2 CTAs/SM (R9-verbatim).
// ---------------------------------------------------------------------------
__global__ __launch_bounds__(256, 2)
void proj_tc_kernel(const float* __restrict__ bo,
                    float* __restrict__ out)
{
    __shared__ __align__(16) uint32_t smem[2 * STG_U];
    const uint32_t sbase = (uint32_t)__cvta_generic_to_shared(smem);

    const int nt = blockIdx.x;
    const int mt = blockIdx.y;

    const int tid  = threadIdx.x;
    const int wid  = tid >> 5;
    const int lane = tid & 31;
    const int wm   = (wid >> 2) * 64;
    const int wn   = (wid & 3) * 32;
    const int grp  = lane >> 2;
    const int qd   = lane & 3;

    float acc[4][4][4];
#pragma unroll
    for (int i = 0; i < 4; i++)
#pragma unroll
        for (int jn = 0; jn < 4; jn++)
#pragma unroll
            for (int c = 0; c < 4; c++)
                acc[i][jn][c] = 0.0f;

    auto stage = [&](int kb, int bf) {
        uint32_t ab = sbase + bf * (STG_U * 4);
        uint32_t bb = ab + ABUF_U * 4;
#pragma unroll
        for (int l = 0; l < 2; l++) {
            int c   = tid + l * 256;
            int row = c >> 2;
            int cc  = c & 3;
            cpasync16(ab + row * (SAU * 4) + cc * 16,
                      g_Oh + (size_t)(mt * 128 + row) * DIM + kb * 32 + cc * 8);
            cpasync16(bb + row * (SAU * 4) + cc * 16,
                      g_Woh + (size_t)(nt * 128 + row) * DIM + kb * 32 + cc * 8);
        }
    };

    stage(0, 0);
    CP_COMMIT();

    int buf = 0;
    for (int kb = 0; kb < DIM / 32; kb++) {
        if (kb + 1 < DIM / 32) {
            stage(kb + 1, buf ^ 1);
            CP_COMMIT();
            CP_WAIT(1);
        } else {
            CP_WAIT(0);
        }
        __syncthreads();

        const uint32_t* Asu = smem + buf * STG_U;
        const uint32_t* Bsu = Asu + ABUF_U;

#pragma unroll
        for (int kk = 0; kk < 2; kk++) {
            const int kp = kk * 8;
            uint32_t a[4][4];
#pragma unroll
            for (int i = 0; i < 4; i++) {
                int r0 = wm + 16 * i + grp;
                a[i][0] = Asu[r0 * SAU + kp + qd];
                a[i][1] = Asu[(r0 + 8) * SAU + kp + qd];
                a[i][2] = Asu[r0 * SAU + kp + qd + 4];
                a[i][3] = Asu[(r0 + 8) * SAU + kp + qd + 4];
            }
            uint32_t b[4][2];
#pragma unroll
            for (int jn = 0; jn < 4; jn++) {
                int n = wn + 8 * jn + grp;
                b[jn][0] = Bsu[n * SAU + kp + qd];
                b[jn][1] = Bsu[n * SAU + kp + qd + 4];
            }
#pragma unroll
            for (int i = 0; i < 4; i++)
#pragma unroll
                for (int jn = 0; jn < 4; jn++)
                    mma_f16(acc[i][jn][0], acc[i][jn][1], acc[i][jn][2], acc[i][jn][3],
                            a[i][0], a[i][1], a[i][2], a[i][3],
                            b[jn][0], b[jn][1]);
        }
        __syncthreads();
        buf ^= 1;
    }

#pragma unroll
    for (int i = 0; i < 4; i++) {
        int r = mt * 128 + wm + 16 * i + grp;
        int b = r / (NJ * SEQT);
        int rem = r - b * (NJ * SEQT);
        int jj = rem >> 8;
        int t  = rem & (SEQT - 1);
        size_t base0 = (((size_t)(b * SEQT + t) * NJ) + jj) * DIM + nt * 128 + wn;
        size_t base1 = base0 + (size_t)8 * NJ * DIM;
#pragma unroll
        for (int jn = 0; jn < 4; jn++) {
            int col = 8 * jn + 2 * qd;
            float2 bb = *(const float2*)(bo + nt * 128 + wn + col);
            *(float2*)&out[base0 + col] = make_float2(acc[i][jn][0] + bb.x,
                                                      acc[i][jn][1] + bb.y);
            *(float2*)&out[base1 + col] = make_float2(acc[i][jn][2] + bb.x,
                                                      acc[i][jn][3] + bb.y);
        }
    }
}

// ---------------------------------------------------------------------------
extern "C" void kernel_launch(void* const* d_in, const int* in_sizes, int n_in,
                              void* d_out, int out_size)
{
    const float* x  = (const float*)d_in[0];
    const float* Wq = (const float*)d_in[1];
    const float* Wk = (const float*)d_in[2];
    const float* Wv = (const float*)d_in[3];
    const float* Wo = (const float*)d_in[4];
    const float* bo = (const float*)d_in[5];
    float* out = (float*)d_out;

    void* xh;  cudaGetSymbolAddress(&xh,  g_Xh);
    void* woh; cudaGetSymbolAddress(&woh, g_Woh);

    // 0) pre-convert to half
    cvt_half_kernel<<<(QKV_ELEMS / 4 + 255) / 256, 256>>>(
        (const float4*)x, (uint2*)xh, QKV_ELEMS / 4);
    cvt_wt_kernel<<<dim3(16, 16, 72), dim3(32, 8)>>>(Wq, Wk, Wv);
    cvt_half_kernel<<<(DIM * DIM / 4 + 255) / 256, 256>>>(
        (const float4*)Wo, (uint2*)woh, DIM * DIM / 4);

    // 1) QKV projection (fp16 + 3-stage cp.async, 2 CTAs/SM)
    cudaFuncSetAttribute(qkv_tc_kernel,
                         cudaFuncAttributeMaxDynamicSharedMemorySize, QKV_SMEM);
    dim3 g1(DIM / 128, (BSZ * SEQT) / 128, 3 * NJ);   // (4, 16, 72)
    qkv_tc_kernel<<<g1, 256, QKV_SMEM>>>();

    // 2) fp16 flash attention
    cudaFuncSetAttribute(attn_tc_kernel,
                         cudaFuncAttributeMaxDynamicSharedMemorySize, ATT_SMEM);
    attn_tc_kernel<<<BSZ * NJ * NH, 512, ATT_SMEM>>>();

    // 3) output projection + bias
    dim3 g3(DIM / 128, (BSZ * SEQT * NJ) / 128);      // (4, 48)
    proj_tc_kernel<<<g3, 256>>>(bo, out);
}

// round 11
// speedup vs baseline: 2.7731x; 1.1613x over previous
#include <cuda_runtime.h>
#include <cuda_fp16.h>
#include <cstdint>

// Problem constants
#define BSZ 8
#define SEQT 256
#define NJ 24
#define DIM 512
#define NH 8
#define HD 64

#define QKV_ELEMS (BSZ * NJ * SEQT * DIM)  // 25,165,824
#define W_ELEMS   (NJ * DIM * DIM)         // 6,291,456

// fp16 operands / intermediates
__device__ __half g_Xh[QKV_ELEMS];       // x, layout [b][t][j][d]
__device__ __half g_Whq[W_ELEMS];        // W transposed: [j][n][k]
__device__ __half g_Whk[W_ELEMS];
__device__ __half g_Whv[W_ELEMS];
__device__ __half g_Woh[DIM * DIM];      // Wo [n][k]
__device__ __half g_Qh[QKV_ELEMS];       // Q pre-scaled by 0.125, [b][j][t][e]
__device__ __half g_Kh[QKV_ELEMS];       // K, [b][j][t][e]
__device__ __half g_Vth[QKV_ELEMS];      // V transposed, [b][j][e][t]
__device__ __half g_Oh[QKV_ELEMS];       // attention out, [b][j][t][e]

__device__ __forceinline__ uint32_t pkh2(float x, float y) {
    __half2 h = __float22half2_rn(make_float2(x, y));
    return *(uint32_t*)&h;
}

__device__ __forceinline__ void mma_f16(
    float& c0, float& c1, float& c2, float& c3,
    uint32_t a0, uint32_t a1, uint32_t a2, uint32_t a3,
    uint32_t b0, uint32_t b1)
{
    asm volatile(
        "mma.sync.aligned.m16n8k16.row.col.f32.f16.f16.f32 "
        "{%0,%1,%2,%3}, {%4,%5,%6,%7}, {%8,%9}, {%0,%1,%2,%3};\n"
        : "+f"(c0), "+f"(c1), "+f"(c2), "+f"(c3)
        : "r"(a0), "r"(a1), "r"(a2), "r"(a3), "r"(b0), "r"(b1));
}

__device__ __forceinline__ void ldsm4(uint32_t& r0, uint32_t& r1,
                                      uint32_t& r2, uint32_t& r3, uint32_t addr)
{
    asm volatile("ldmatrix.sync.aligned.m8n8.x4.shared.b16 {%0,%1,%2,%3}, [%4];"
                 : "=r"(r0), "=r"(r1), "=r"(r2), "=r"(r3) : "r"(addr));
}

__device__ __forceinline__ void cpasync16(uint32_t dst, const void* src) {
    asm volatile("cp.async.cg.shared.global [%0], [%1], 16;\n"
                 :: "r"(dst), "l"(src));
}
#define CP_COMMIT() asm volatile("cp.async.commit_group;\n" ::: "memory")
#define CP_WAIT(N)  asm volatile("cp.async.wait_group %0;\n" :: "n"(N) : "memory")

// fp16 GEMM smem: u32(=half2) rows, stride 20 u32 (16 data + 4 pad)
#define SAU 20
#define ABUF_U (128 * SAU)          // 2560 u32
#define STG_U  (2 * ABUF_U)         // 5120 u32 = 20480 B per stage
#define QKV_SMEM (3 * STG_U * 4)    // 61440 B (3-stage)

// ---------------------------------------------------------------------------
// Pre-pass kernels
// ---------------------------------------------------------------------------
__global__ __launch_bounds__(256)
void cvt_half_kernel(const float4* __restrict__ in, uint2* __restrict__ out, int n4)
{
    int i = blockIdx.x * blockDim.x + threadIdx.x;
    if (i < n4) {
        float4 v = in[i];
        out[i] = make_uint2(pkh2(v.x, v.y), pkh2(v.z, v.w));
    }
}

// Transpose W[j][k][n] (f32) -> Wh[j][n][k] (half). grid (16,16,72), block (32,8)
__global__ __launch_bounds__(256)
void cvt_wt_kernel(const float* __restrict__ Wq,
                   const float* __restrict__ Wk,
                   const float* __restrict__ Wv)
{
    __shared__ float tile[32][33];
    const int z = blockIdx.z;
    const int j = z % NJ;
    const int p = z / NJ;
    const float* W = (p == 0) ? Wq : ((p == 1) ? Wk : Wv);
    __half* Wh     = (p == 0) ? g_Whq : ((p == 1) ? g_Whk : g_Whv);

    const int n0 = blockIdx.x * 32;
    const int k0 = blockIdx.y * 32;
    const int tx = threadIdx.x;
    const int ty = threadIdx.y;
    const size_t base = (size_t)j * DIM * DIM;

#pragma unroll
    for (int i = 0; i < 4; i++)
        tile[ty + 8 * i][tx] = W[base + (size_t)(k0 + ty + 8 * i) * DIM + n0 + tx];
    __syncthreads();
#pragma unroll
    for (int i = 0; i < 4; i++)
        Wh[base + (size_t)(n0 + ty + 8 * i) * DIM + k0 + tx] =
            __float2half(tile[tx][ty + 8 * i]);
}

// ---------------------------------------------------------------------------
// Kernel 1: per-joint Q/K/V projection, fp16 m16n8k16 + 3-stage cp.async +
// ldmatrix fragment loads. Block 128x128, BK=32, 256 threads, 2 CTAs/SM.
// grid: (4, 16, 72)
// ---------------------------------------------------------------------------
__global__ __launch_bounds__(256, 2)
void qkv_tc_kernel()
{
    extern __shared__ uint32_t smem[];
    const uint32_t sbase = (uint32_t)__cvta_generic_to_shared(smem);

    const int nt = blockIdx.x;
    const int mt = blockIdx.y;
    const int z  = blockIdx.z;
    const int j  = z % NJ;
    const int p  = z / NJ;

    const __half* Wh = (p == 0) ? g_Whq : ((p == 1) ? g_Whk : g_Whv);

    const int tid  = threadIdx.x;
    const int wid  = tid >> 5;
    const int lane = tid & 31;
    const int wm   = (wid >> 2) * 64;
    const int wn   = (wid & 3) * 32;
    const int grp  = lane >> 2;
    const int qd   = lane & 3;

    // ldmatrix per-lane address components (u32 units)
    const int a_row = (lane & 15);           // row within 16-row A matrix pair
    const int a_k   = 4 * (lane >> 4);       // +0 or +4 (k8 half)
    const int b_n   = (lane & 7) + 8 * (lane >> 4);   // n within 16-col pair
    const int b_k   = 4 * ((lane >> 3) & 1);

    const size_t wbase = (size_t)j * DIM * DIM + (size_t)nt * 128 * DIM;

    float acc[4][4][4];
#pragma unroll
    for (int i = 0; i < 4; i++)
#pragma unroll
        for (int jn = 0; jn < 4; jn++)
#pragma unroll
            for (int c = 0; c < 4; c++)
                acc[i][jn][c] = 0.0f;

    auto stage = [&](int kb, int bf) {
        uint32_t ab = sbase + bf * (STG_U * 4);
        uint32_t bb = ab + ABUF_U * 4;
#pragma unroll
        for (int l = 0; l < 2; l++) {
            int c   = tid + l * 256;
            int row = c >> 2;
            int cc  = c & 3;
            cpasync16(ab + row * (SAU * 4) + cc * 16,
                      g_Xh + ((size_t)(mt * 128 + row) * NJ + j) * DIM + kb * 32 + cc * 8);
            cpasync16(bb + row * (SAU * 4) + cc * 16,
                      Wh + wbase + (size_t)row * DIM + kb * 32 + cc * 8);
        }
    };

    stage(0, 0);
    CP_COMMIT();
    stage(1, 1);
    CP_COMMIT();

    for (int kb = 0; kb < DIM / 32; kb++) {
        if (kb < DIM / 32 - 1) { CP_WAIT(1); } else { CP_WAIT(0); }
        __syncthreads();
        if (kb + 2 < DIM / 32) {
            stage(kb + 2, (kb + 2) % 3);
            CP_COMMIT();
        }

        const uint32_t abase = sbase + (kb % 3) * (STG_U * 4);
        const uint32_t bbase = abase + ABUF_U * 4;

#pragma unroll
        for (int kk = 0; kk < 2; kk++) {
            const int kp = kk * 8;
            uint32_t a[4][4];
#pragma unroll
            for (int i = 0; i < 4; i++) {
                uint32_t addr = abase +
                    ((wm + 16 * i + a_row) * SAU + kp + a_k) * 4;
                ldsm4(a[i][0], a[i][1], a[i][2], a[i][3], addr);
            }
            uint32_t b[4][2];
#pragma unroll
            for (int jp = 0; jp < 2; jp++) {
                uint32_t addr = bbase +
                    ((wn + 16 * jp + b_n) * SAU + kp + b_k) * 4;
                ldsm4(b[2 * jp][0], b[2 * jp][1], b[2 * jp + 1][0], b[2 * jp + 1][1], addr);
            }
#pragma unroll
            for (int i = 0; i < 4; i++)
#pragma unroll
                for (int jn = 0; jn < 4; jn++)
                    mma_f16(acc[i][jn][0], acc[i][jn][1], acc[i][jn][2], acc[i][jn][3],
                            a[i][0], a[i][1], a[i][2], a[i][3],
                            b[jn][0], b[jn][1]);
        }
    }

    // Epilogue
    if (p < 2) {
        __half* outh = (p == 0) ? g_Qh : g_Kh;
        const float scl = (p == 0) ? 0.125f : 1.0f;
#pragma unroll
        for (int i = 0; i < 4; i++) {
            int m = mt * 128 + wm + 16 * i + grp;
            int b = m >> 8;
            int t = m & (SEQT - 1);
            size_t r0 = (((size_t)(b * NJ + j) * SEQT) + t) * DIM + nt * 128 + wn;
            size_t r1 = r0 + (size_t)8 * DIM;
#pragma unroll
            for (int jn = 0; jn < 4; jn++) {
                int col = 8 * jn + 2 * qd;
                *(uint32_t*)&outh[r0 + col] = pkh2(acc[i][jn][0] * scl, acc[i][jn][1] * scl);
                *(uint32_t*)&outh[r1 + col] = pkh2(acc[i][jn][2] * scl, acc[i][jn][3] * scl);
            }
        }
    } else {
        // V transposed: [b][j][e][t]
#pragma unroll
        for (int i = 0; i < 4; i++) {
            int m = mt * 128 + wm + 16 * i + grp;
            int b = m >> 8;
            int t = m & (SEQT - 1);
#pragma unroll
            for (int jn = 0; jn < 4; jn++) {
                int e = nt * 128 + wn + 8 * jn + 2 * qd;
                size_t base = ((size_t)(b * NJ + j) * DIM + e) * SEQT + t;
                g_Vth[base]            = __float2half(acc[i][jn][0]);
                g_Vth[base + SEQT]     = __float2half(acc[i][jn][1]);
                g_Vth[base + 8]        = __float2half(acc[i][jn][2]);
                g_Vth[base + SEQT + 8] = __float2half(acc[i][jn][3]);
            }
        }
    }
}

// ---------------------------------------------------------------------------
// Kernel 2: fp16 flash attention with ldmatrix fragment loads.
// ---------------------------------------------------------------------------
#define AQ_ST 36     // Q/K row stride in u32 (32 data + 4 pad)
#define AV_ST 132    // Vt row stride in u32 (128 data + 4 pad)
#define ATT_U (2 * SEQT * AQ_ST + HD * AV_ST)   // 26880 u32
#define ATT_SMEM (ATT_U * 4)                    // 107520 B

__global__ __launch_bounds__(512)
void attn_tc_kernel()
{
    extern __shared__ uint32_t smu[];
    const uint32_t sbase = (uint32_t)__cvta_generic_to_shared(smu);
    const uint32_t qs_b = sbase;
    const uint32_t ks_b = sbase + SEQT * AQ_ST * 4;
    const uint32_t vt_b = sbase + 2 * SEQT * AQ_ST * 4;

    const int bjh = blockIdx.x;
    const int h   = bjh & (NH - 1);
    const int bj  = bjh >> 3;
    const int tid  = threadIdx.x;
    const int wid  = tid >> 5;
    const int lane = tid & 31;
    const int grp  = lane >> 2;
    const int qd   = lane & 3;
    const int m0   = wid * 16;

    const int a_row = (lane & 15);
    const int a_k   = 4 * (lane >> 4);
    const int b_n   = (lane & 7) + 8 * (lane >> 4);
    const int b_k   = 4 * ((lane >> 3) & 1);

    const __half* qg = g_Qh + (size_t)bj * SEQT * DIM + h * HD;
    const __half* kg = g_Kh + (size_t)bj * SEQT * DIM + h * HD;
    const __half* vg = g_Vth + (size_t)bj * DIM * SEQT + (size_t)h * HD * SEQT;

    // Stage Q, K: 256 rows x 8 uint4; Vt: 64 rows x 32 uint4
#pragma unroll
    for (int l = 0; l < 4; l++) {
        int idx = tid + l * 512;
        int row = idx >> 3;
        int q4  = idx & 7;
        cpasync16(qs_b + (row * AQ_ST + q4 * 4) * 4, qg + (size_t)row * DIM + q4 * 8);
        cpasync16(ks_b + (row * AQ_ST + q4 * 4) * 4, kg + (size_t)row * DIM + q4 * 8);
    }
#pragma unroll
    for (int l = 0; l < 4; l++) {
        int idx = tid + l * 512;
        int d  = idx >> 5;
        int q4 = idx & 31;
        cpasync16(vt_b + (d * AV_ST + q4 * 4) * 4, vg + (size_t)d * SEQT + q4 * 8);
    }
    CP_COMMIT();
    CP_WAIT(0);
    __syncthreads();

    float oacc[8][4];
#pragma unroll
    for (int jn = 0; jn < 8; jn++)
#pragma unroll
        for (int c = 0; c < 4; c++) oacc[jn][c] = 0.0f;
    float mrow[2] = { -1e30f, -1e30f };
    float lrow[2] = { 0.0f, 0.0f };

    for (int ch = 0; ch < 4; ch++) {
        // ---- S = Q K^T over this 64-key chunk (Q pre-scaled) ----
        float sacc[8][4];
#pragma unroll
        for (int jn = 0; jn < 8; jn++)
#pragma unroll
            for (int c = 0; c < 4; c++) sacc[jn][c] = 0.0f;

#pragma unroll
        for (int kt = 0; kt < 4; kt++) {
            const int kp = kt * 8;
            uint32_t a0, a1, a2, a3;
            ldsm4(a0, a1, a2, a3,
                  qs_b + ((m0 + a_row) * AQ_ST + kp + a_k) * 4);
#pragma unroll
            for (int jp = 0; jp < 4; jp++) {
                uint32_t b00, b01, b10, b11;
                ldsm4(b00, b01, b10, b11,
                      ks_b + ((ch * 64 + 16 * jp + b_n) * AQ_ST + kp + b_k) * 4);
                mma_f16(sacc[2 * jp][0], sacc[2 * jp][1], sacc[2 * jp][2], sacc[2 * jp][3],
                        a0, a1, a2, a3, b00, b01);
                mma_f16(sacc[2 * jp + 1][0], sacc[2 * jp + 1][1],
                        sacc[2 * jp + 1][2], sacc[2 * jp + 1][3],
                        a0, a1, a2, a3, b10, b11);
            }
        }

        // ---- online softmax (branchless, per-lane partial l) ----
#pragma unroll
        for (int r = 0; r < 2; r++) {
            float mx = -1e30f;
#pragma unroll
            for (int jn = 0; jn < 8; jn++) {
                mx = fmaxf(mx, sacc[jn][2 * r]);
                mx = fmaxf(mx, sacc[jn][2 * r + 1]);
            }
            mx = fmaxf(mx, __shfl_xor_sync(0xffffffffu, mx, 1));
            mx = fmaxf(mx, __shfl_xor_sync(0xffffffffu, mx, 2));
            float mnew = fmaxf(mrow[r], mx);
            float scale = __expf(mrow[r] - mnew);
            mrow[r] = mnew;
            float ps = 0.0f;
#pragma unroll
            for (int jn = 0; jn < 8; jn++) {
                float p0 = __expf(sacc[jn][2 * r] - mnew);
                float p1 = __expf(sacc[jn][2 * r + 1] - mnew);
                sacc[jn][2 * r] = p0;
                sacc[jn][2 * r + 1] = p1;
                ps += p0 + p1;
                oacc[jn][2 * r] *= scale;
                oacc[jn][2 * r + 1] *= scale;
            }
            lrow[r] = lrow[r] * scale + ps;
        }

        // ---- O += P V : P C-frag -> fp16 A-frag by local packing ----
#pragma unroll
        for (int kt = 0; kt < 4; kt++) {
            uint32_t a0 = pkh2(sacc[2 * kt][0], sacc[2 * kt][1]);
            uint32_t a1 = pkh2(sacc[2 * kt][2], sacc[2 * kt][3]);
            uint32_t a2 = pkh2(sacc[2 * kt + 1][0], sacc[2 * kt + 1][1]);
            uint32_t a3 = pkh2(sacc[2 * kt + 1][2], sacc[2 * kt + 1][3]);
            const int kp = ch * 32 + kt * 8;
#pragma unroll
            for (int jp = 0; jp < 4; jp++) {
                uint32_t b00, b01, b10, b11;
                ldsm4(b00, b01, b10, b11,
                      vt_b + ((16 * jp + b_n) * AV_ST + kp + b_k) * 4);
                mma_f16(oacc[2 * jp][0], oacc[2 * jp][1], oacc[2 * jp][2], oacc[2 * jp][3],
                        a0, a1, a2, a3, b00, b01);
                mma_f16(oacc[2 * jp + 1][0], oacc[2 * jp + 1][1],
                        oacc[2 * jp + 1][2], oacc[2 * jp + 1][3],
                        a0, a1, a2, a3, b10, b11);
            }
        }
    }

    // ---- finalize: reduce l over quad, normalize, store half ----
    float inv[2];
#pragma unroll
    for (int r = 0; r < 2; r++) {
        float lr = lrow[r];
        lr += __shfl_xor_sync(0xffffffffu, lr, 1);
        lr += __shfl_xor_sync(0xffffffffu, lr, 2);
        inv[r] = 1.0f / lr;
    }
    const size_t obase = (size_t)bj * SEQT * DIM + h * HD;
    __half* o0 = g_Oh + obase + (size_t)(m0 + grp) * DIM;
    __half* o1 = g_Oh + obase + (size_t)(m0 + grp + 8) * DIM;
#pragma unroll
    for (int jn = 0; jn < 8; jn++) {
        int col = 8 * jn + 2 * qd;
        *(uint32_t*)&o0[col] = pkh2(oacc[jn][0] * inv[0], oacc[jn][1] * inv[0]);
        *(uint32_t*)&o1[col] = pkh2(oacc[jn][2] * inv[1], oacc[jn][3] * inv[1]);
    }
}

// ---------------------------------------------------------------------------
// Kernel 3: output projection + bias, fp16 + cp.async + ldmatrix, 2 CTAs/SM.
// ---------------------------------------------------------------------------
__global__ __launch_bounds__(256, 2)
void proj_tc_kernel(const float* __restrict__ bo,
                    float* __restrict__ out)
{
    __shared__ __align__(16) uint32_t smem[2 * STG_U];
    const uint32_t sbase = (uint32_t)__cvta_generic_to_shared(smem);

    const int nt = blockIdx.x;
    const int mt = blockIdx.y;

    const int tid  = threadIdx.x;
    const int wid  = tid >> 5;
    const int lane = tid & 31;
    const int wm   = (wid >> 2) * 64;
    const int wn   = (wid & 3) * 32;
    const int grp  = lane >> 2;
    const int qd   = lane & 3;

    const int a_row = (lane & 15);
    const int a_k   = 4 * (lane >> 4);
    const int b_n   = (lane & 7) + 8 * (lane >> 4);
    const int b_k   = 4 * ((lane >> 3) & 1);

    float acc[4][4][4];
#pragma unroll
    for (int i = 0; i < 4; i++)
#pragma unroll
        for (int jn = 0; jn < 4; jn++)
#pragma unroll
            for (int c = 0; c < 4; c++)
                acc[i][jn][c] = 0.0f;

    auto stage = [&](int kb, int bf) {
        uint32_t ab = sbase + bf * (STG_U * 4);
        uint32_t bb = ab + ABUF_U * 4;
#pragma unroll
        for (int l = 0; l < 2; l++) {
            int c   = tid + l * 256;
            int row = c >> 2;
            int cc  = c & 3;
            cpasync16(ab + row * (SAU * 4) + cc * 16,
                      g_Oh + (size_t)(mt * 128 + row) * DIM + kb * 32 + cc * 8);
            cpasync16(bb + row * (SAU * 4) + cc * 16,
                      g_Woh + (size_t)(nt * 128 + row) * DIM + kb * 32 + cc * 8);
        }
    };

    stage(0, 0);
    CP_COMMIT();

    int buf = 0;
    for (int kb = 0; kb < DIM / 32; kb++) {
        if (kb + 1 < DIM / 32) {
            stage(kb + 1, buf ^ 1);
            CP_COMMIT();
            CP_WAIT(1);
        } else {
            CP_WAIT(0);
        }
        __syncthreads();

        const uint32_t abase = sbase + buf * (STG_U * 4);
        const uint32_t bbase = abase + ABUF_U * 4;

#pragma unroll
        for (int kk = 0; kk < 2; kk++) {
            const int kp = kk * 8;
            uint32_t a[4][4];
#pragma unroll
            for (int i = 0; i < 4; i++) {
                uint32_t addr = abase +
                    ((wm + 16 * i + a_row) * SAU + kp + a_k) * 4;
                ldsm4(a[i][0], a[i][1], a[i][2], a[i][3], addr);
            }
            uint32_t b[4][2];
#pragma unroll
            for (int jp = 0; jp < 2; jp++) {
                uint32_t addr = bbase +
                    ((wn + 16 * jp + b_n) * SAU + kp + b_k) * 4;
                ldsm4(b[2 * jp][0], b[2 * jp][1], b[2 * jp + 1][0], b[2 * jp + 1][1], addr);
            }
#pragma unroll
            for (int i = 0; i < 4; i++)
#pragma unroll
                for (int jn = 0; jn < 4; jn++)
                    mma_f16(acc[i][jn][0], acc[i][jn][1], acc[i][jn][2], acc[i][jn][3],
                            a[i][0], a[i][1], a[i][2], a[i][3],
                            b[jn][0], b[jn][1]);
        }
        __syncthreads();
        buf ^= 1;
    }

#pragma unroll
    for (int i = 0; i < 4; i++) {
        int r = mt * 128 + wm + 16 * i + grp;
        int b = r / (NJ * SEQT);
        int rem = r - b * (NJ * SEQT);
        int jj = rem >> 8;
        int t  = rem & (SEQT - 1);
        size_t base0 = (((size_t)(b * SEQT + t) * NJ) + jj) * DIM + nt * 128 + wn;
        size_t base1 = base0 + (size_t)8 * NJ * DIM;
#pragma unroll
        for (int jn = 0; jn < 4; jn++) {
            int col = 8 * jn + 2 * qd;
            float2 bb = *(const float2*)(bo + nt * 128 + wn + col);
            *(float2*)&out[base0 + col] = make_float2(acc[i][jn][0] + bb.x,
                                                      acc[i][jn][1] + bb.y);
            *(float2*)&out[base1 + col] = make_float2(acc[i][jn][2] + bb.x,
                                                      acc[i][jn][3] + bb.y);
        }
    }
}

// ---------------------------------------------------------------------------
extern "C" void kernel_launch(void* const* d_in, const int* in_sizes, int n_in,
                              void* d_out, int out_size)
{
    const float* x  = (const float*)d_in[0];
    const float* Wq = (const float*)d_in[1];
    const float* Wk = (const float*)d_in[2];
    const float* Wv = (const float*)d_in[3];
    const float* Wo = (const float*)d_in[4];
    const float* bo = (const float*)d_in[5];
    float* out = (float*)d_out;

    void* xh;  cudaGetSymbolAddress(&xh,  g_Xh);
    void* woh; cudaGetSymbolAddress(&woh, g_Woh);

    // 0) pre-convert to half
    cvt_half_kernel<<<(QKV_ELEMS / 4 + 255) / 256, 256>>>(
        (const float4*)x, (uint2*)xh, QKV_ELEMS / 4);
    cvt_wt_kernel<<<dim3(16, 16, 72), dim3(32, 8)>>>(Wq, Wk, Wv);
    cvt_half_kernel<<<(DIM * DIM / 4 + 255) / 256, 256>>>(
        (const float4*)Wo, (uint2*)woh, DIM * DIM / 4);

    // 1) QKV projection (fp16 + 3-stage cp.async + ldmatrix, 2 CTAs/SM)
    cudaFuncSetAttribute(qkv_tc_kernel,
                         cudaFuncAttributeMaxDynamicSharedMemorySize, QKV_SMEM);
    dim3 g1(DIM / 128, (BSZ * SEQT) / 128, 3 * NJ);   // (4, 16, 72)
    qkv_tc_kernel<<<g1, 256, QKV_SMEM>>>();

    // 2) fp16 flash attention (ldmatrix)
    cudaFuncSetAttribute(attn_tc_kernel,
                         cudaFuncAttributeMaxDynamicSharedMemorySize, ATT_SMEM);
    attn_tc_kernel<<<BSZ * NJ * NH, 512, ATT_SMEM>>>();

    // 3) output projection + bias (ldmatrix)
    dim3 g3(DIM / 128, (BSZ * SEQT * NJ) / 128);      // (4, 48)
    proj_tc_kernel<<<g3, 256>>>(bo, out);
}

// round 12
// speedup vs baseline: 2.8225x; 1.0178x over previous
#include <cuda_runtime.h>
#include <cuda_fp16.h>
#include <cstdint>

// Problem constants
#define BSZ 8
#define SEQT 256
#define NJ 24
#define DIM 512
#define NH 8
#define HD 64

#define QKV_ELEMS (BSZ * NJ * SEQT * DIM)  // 25,165,824
#define W_ELEMS   (NJ * DIM * DIM)         // 6,291,456

// fp16 operands / intermediates
__device__ __half g_Xh[QKV_ELEMS];       // x, layout [b][t][j][d]
__device__ __half g_Whq[W_ELEMS];        // W transposed: [j][n][k]
__device__ __half g_Whk[W_ELEMS];
__device__ __half g_Whv[W_ELEMS];
__device__ __half g_Woh[DIM * DIM];      // Wo [n][k]
__device__ __half g_Qh[QKV_ELEMS];       // Q pre-scaled by 0.125, [b][j][t][e]
__device__ __half g_Kh[QKV_ELEMS];       // K, [b][j][t][e]
__device__ __half g_Vth[QKV_ELEMS];      // V transposed, [b][j][e][t]
__device__ __half g_Oh[QKV_ELEMS];       // attention out, [b][j][t][e]

__device__ __forceinline__ uint32_t pkh2(float x, float y) {
    __half2 h = __float22half2_rn(make_float2(x, y));
    return *(uint32_t*)&h;
}

__device__ __forceinline__ void mma_f16(
    float& c0, float& c1, float& c2, float& c3,
    uint32_t a0, uint32_t a1, uint32_t a2, uint32_t a3,
    uint32_t b0, uint32_t b1)
{
    asm volatile(
        "mma.sync.aligned.m16n8k16.row.col.f32.f16.f16.f32 "
        "{%0,%1,%2,%3}, {%4,%5,%6,%7}, {%8,%9}, {%0,%1,%2,%3};\n"
        : "+f"(c0), "+f"(c1), "+f"(c2), "+f"(c3)
        : "r"(a0), "r"(a1), "r"(a2), "r"(a3), "r"(b0), "r"(b1));
}

__device__ __forceinline__ void ldsm4(uint32_t& r0, uint32_t& r1,
                                      uint32_t& r2, uint32_t& r3, uint32_t addr)
{
    asm volatile("ldmatrix.sync.aligned.m8n8.x4.shared.b16 {%0,%1,%2,%3}, [%4];"
                 : "=r"(r0), "=r"(r1), "=r"(r2), "=r"(r3) : "r"(addr));
}

__device__ __forceinline__ void cpasync16(uint32_t dst, const void* src) {
    asm volatile("cp.async.cg.shared.global [%0], [%1], 16;\n"
                 :: "r"(dst), "l"(src));
}
#define CP_COMMIT() asm volatile("cp.async.commit_group;\n" ::: "memory")
#define CP_WAIT(N)  asm volatile("cp.async.wait_group %0;\n" :: "n"(N) : "memory")

// BK=64 GEMM smem: u32(=half2) rows, stride 36 u32 (32 data + 4 pad)
// ldmatrix 16B-group = 9*m mod 8 -> all distinct (conflict-free)
#define SAU 36
#define ABUF_U (128 * SAU)          // 4608 u32
#define STG_U  (2 * ABUF_U)         // 9216 u32 = 36864 B per stage
#define GEMM_SMEM (3 * STG_U * 4)   // 110592 B (3-stage ring)

// ---------------------------------------------------------------------------
// Pre-pass kernels
// ---------------------------------------------------------------------------
__global__ __launch_bounds__(256)
void cvt_half_kernel(const float4* __restrict__ in, uint2* __restrict__ out, int n4)
{
    int i = blockIdx.x * blockDim.x + threadIdx.x;
    if (i < n4) {
        float4 v = in[i];
        out[i] = make_uint2(pkh2(v.x, v.y), pkh2(v.z, v.w));
    }
}

// Transpose W[j][k][n] (f32) -> Wh[j][n][k] (half). grid (16,16,72), block (32,8)
__global__ __launch_bounds__(256)
void cvt_wt_kernel(const float* __restrict__ Wq,
                   const float* __restrict__ Wk,
                   const float* __restrict__ Wv)
{
    __shared__ float tile[32][33];
    const int z = blockIdx.z;
    const int j = z % NJ;
    const int p = z / NJ;
    const float* W = (p == 0) ? Wq : ((p == 1) ? Wk : Wv);
    __half* Wh     = (p == 0) ? g_Whq : ((p == 1) ? g_Whk : g_Whv);

    const int n0 = blockIdx.x * 32;
    const int k0 = blockIdx.y * 32;
    const int tx = threadIdx.x;
    const int ty = threadIdx.y;
    const size_t base = (size_t)j * DIM * DIM;

#pragma unroll
    for (int i = 0; i < 4; i++)
        tile[ty + 8 * i][tx] = W[base + (size_t)(k0 + ty + 8 * i) * DIM + n0 + tx];
    __syncthreads();
#pragma unroll
    for (int i = 0; i < 4; i++)
        Wh[base + (size_t)(n0 + ty + 8 * i) * DIM + k0 + tx] =
            __float2half(tile[tx][ty + 8 * i]);
}

// ---------------------------------------------------------------------------
// Kernel 1: per-joint Q/K/V projection, fp16 m16n8k16, BK=64, 3-stage
// cp.async ring + ldmatrix. Block 128x128, 256 threads, 2 CTAs/SM.
// grid: (4, 16, 72)
// ---------------------------------------------------------------------------
__global__ __launch_bounds__(256, 2)
void qkv_tc_kernel()
{
    extern __shared__ uint32_t smem[];
    const uint32_t sbase = (uint32_t)__cvta_generic_to_shared(smem);

    const int nt = blockIdx.x;
    const int mt = blockIdx.y;
    const int z  = blockIdx.z;
    const int j  = z % NJ;
    const int p  = z / NJ;

    const __half* Wh = (p == 0) ? g_Whq : ((p == 1) ? g_Whk : g_Whv);

    const int tid  = threadIdx.x;
    const int wid  = tid >> 5;
    const int lane = tid & 31;
    const int wm   = (wid >> 2) * 64;
    const int wn   = (wid & 3) * 32;
    const int grp  = lane >> 2;
    const int qd   = lane & 3;

    // ldmatrix per-lane address components (u32 units)
    const int a_row = (lane & 15);
    const int a_k   = 4 * (lane >> 4);
    const int b_n   = (lane & 7) + 8 * (lane >> 4);
    const int b_k   = 4 * ((lane >> 3) & 1);

    const size_t wbase = (size_t)j * DIM * DIM + (size_t)nt * 128 * DIM;

    float acc[4][4][4];
#pragma unroll
    for (int i = 0; i < 4; i++)
#pragma unroll
        for (int jn = 0; jn < 4; jn++)
#pragma unroll
            for (int c = 0; c < 4; c++)
                acc[i][jn][c] = 0.0f;

    auto stage = [&](int kb, int bf) {
        uint32_t ab = sbase + bf * (STG_U * 4);
        uint32_t bb = ab + ABUF_U * 4;
#pragma unroll
        for (int l = 0; l < 4; l++) {
            int c   = tid + l * 256;    // 0..1023
            int row = c >> 3;           // 0..127
            int cc  = c & 7;            // 16B chunk within 64-half row
            cpasync16(ab + row * (SAU * 4) + cc * 16,
                      g_Xh + ((size_t)(mt * 128 + row) * NJ + j) * DIM + kb * 64 + cc * 8);
            cpasync16(bb + row * (SAU * 4) + cc * 16,
                      Wh + wbase + (size_t)row * DIM + kb * 64 + cc * 8);
        }
    };

    stage(0, 0);
    CP_COMMIT();
    stage(1, 1);
    CP_COMMIT();

    const int NKB = DIM / 64;   // 8
    for (int kb = 0; kb < NKB; kb++) {
        if (kb < NKB - 1) { CP_WAIT(1); } else { CP_WAIT(0); }
        __syncthreads();
        if (kb + 2 < NKB) {
            stage(kb + 2, (kb + 2) % 3);
            CP_COMMIT();
        }

        const uint32_t abase = sbase + (kb % 3) * (STG_U * 4);
        const uint32_t bbase = abase + ABUF_U * 4;

#pragma unroll
        for (int kk = 0; kk < 4; kk++) {
            const int kp = kk * 8;
            uint32_t a[4][4];
#pragma unroll
            for (int i = 0; i < 4; i++) {
                uint32_t addr = abase +
                    ((wm + 16 * i + a_row) * SAU + kp + a_k) * 4;
                ldsm4(a[i][0], a[i][1], a[i][2], a[i][3], addr);
            }
            uint32_t b[4][2];
#pragma unroll
            for (int jp = 0; jp < 2; jp++) {
                uint32_t addr = bbase +
                    ((wn + 16 * jp + b_n) * SAU + kp + b_k) * 4;
                ldsm4(b[2 * jp][0], b[2 * jp][1], b[2 * jp + 1][0], b[2 * jp + 1][1], addr);
            }
#pragma unroll
            for (int i = 0; i < 4; i++)
#pragma unroll
                for (int jn = 0; jn < 4; jn++)
                    mma_f16(acc[i][jn][0], acc[i][jn][1], acc[i][jn][2], acc[i][jn][3],
                            a[i][0], a[i][1], a[i][2], a[i][3],
                            b[jn][0], b[jn][1]);
        }
    }

    // Epilogue
    if (p < 2) {
        __half* outh = (p == 0) ? g_Qh : g_Kh;
        const float scl = (p == 0) ? 0.125f : 1.0f;
#pragma unroll
        for (int i = 0; i < 4; i++) {
            int m = mt * 128 + wm + 16 * i + grp;
            int b = m >> 8;
            int t = m & (SEQT - 1);
            size_t r0 = (((size_t)(b * NJ + j) * SEQT) + t) * DIM + nt * 128 + wn;
            size_t r1 = r0 + (size_t)8 * DIM;
#pragma unroll
            for (int jn = 0; jn < 4; jn++) {
                int col = 8 * jn + 2 * qd;
                *(uint32_t*)&outh[r0 + col] = pkh2(acc[i][jn][0] * scl, acc[i][jn][1] * scl);
                *(uint32_t*)&outh[r1 + col] = pkh2(acc[i][jn][2] * scl, acc[i][jn][3] * scl);
            }
        }
    } else {
        // V transposed: [b][j][e][t]
#pragma unroll
        for (int i = 0; i < 4; i++) {
            int m = mt * 128 + wm + 16 * i + grp;
            int b = m >> 8;
            int t = m & (SEQT - 1);
#pragma unroll
            for (int jn = 0; jn < 4; jn++) {
                int e = nt * 128 + wn + 8 * jn + 2 * qd;
                size_t base = ((size_t)(b * NJ + j) * DIM + e) * SEQT + t;
                g_Vth[base]            = __float2half(acc[i][jn][0]);
                g_Vth[base + SEQT]     = __float2half(acc[i][jn][1]);
                g_Vth[base + 8]        = __float2half(acc[i][jn][2]);
                g_Vth[base + SEQT + 8] = __float2half(acc[i][jn][3]);
            }
        }
    }
}

// ---------------------------------------------------------------------------
// Kernel 2: fp16 flash attention with ldmatrix fragment loads (R11-verbatim).
// ---------------------------------------------------------------------------
#define AQ_ST 36     // Q/K row stride in u32 (32 data + 4 pad)
#define AV_ST 132    // Vt row stride in u32 (128 data + 4 pad)
#define ATT_U (2 * SEQT * AQ_ST + HD * AV_ST)   // 26880 u32
#define ATT_SMEM (ATT_U * 4)                    // 107520 B

__global__ __launch_bounds__(512)
void attn_tc_kernel()
{
    extern __shared__ uint32_t smu[];
    const uint32_t sbase = (uint32_t)__cvta_generic_to_shared(smu);
    const uint32_t qs_b = sbase;
    const uint32_t ks_b = sbase + SEQT * AQ_ST * 4;
    const uint32_t vt_b = sbase + 2 * SEQT * AQ_ST * 4;

    const int bjh = blockIdx.x;
    const int h   = bjh & (NH - 1);
    const int bj  = bjh >> 3;
    const int tid  = threadIdx.x;
    const int wid  = tid >> 5;
    const int lane = tid & 31;
    const int grp  = lane >> 2;
    const int qd   = lane & 3;
    const int m0   = wid * 16;

    const int a_row = (lane & 15);
    const int a_k   = 4 * (lane >> 4);
    const int b_n   = (lane & 7) + 8 * (lane >> 4);
    const int b_k   = 4 * ((lane >> 3) & 1);

    const __half* qg = g_Qh + (size_t)bj * SEQT * DIM + h * HD;
    const __half* kg = g_Kh + (size_t)bj * SEQT * DIM + h * HD;
    const __half* vg = g_Vth + (size_t)bj * DIM * SEQT + (size_t)h * HD * SEQT;

#pragma unroll
    for (int l = 0; l < 4; l++) {
        int idx = tid + l * 512;
        int row = idx >> 3;
        int q4  = idx & 7;
        cpasync16(qs_b + (row * AQ_ST + q4 * 4) * 4, qg + (size_t)row * DIM + q4 * 8);
        cpasync16(ks_b + (row * AQ_ST + q4 * 4) * 4, kg + (size_t)row * DIM + q4 * 8);
    }
#pragma unroll
    for (int l = 0; l < 4; l++) {
        int idx = tid + l * 512;
        int d  = idx >> 5;
        int q4 = idx & 31;
        cpasync16(vt_b + (d * AV_ST + q4 * 4) * 4, vg + (size_t)d * SEQT + q4 * 8);
    }
    CP_COMMIT();
    CP_WAIT(0);
    __syncthreads();

    float oacc[8][4];
#pragma unroll
    for (int jn = 0; jn < 8; jn++)
#pragma unroll
        for (int c = 0; c < 4; c++) oacc[jn][c] = 0.0f;
    float mrow[2] = { -1e30f, -1e30f };
    float lrow[2] = { 0.0f, 0.0f };

    for (int ch = 0; ch < 4; ch++) {
        float sacc[8][4];
#pragma unroll
        for (int jn = 0; jn < 8; jn++)
#pragma unroll
            for (int c = 0; c < 4; c++) sacc[jn][c] = 0.0f;

#pragma unroll
        for (int kt = 0; kt < 4; kt++) {
            const int kp = kt * 8;
            uint32_t a0, a1, a2, a3;
            ldsm4(a0, a1, a2, a3,
                  qs_b + ((m0 + a_row) * AQ_ST + kp + a_k) * 4);
#pragma unroll
            for (int jp = 0; jp < 4; jp++) {
                uint32_t b00, b01, b10, b11;
                ldsm4(b00, b01, b10, b11,
                      ks_b + ((ch * 64 + 16 * jp + b_n) * AQ_ST + kp + b_k) * 4);
                mma_f16(sacc[2 * jp][0], sacc[2 * jp][1], sacc[2 * jp][2], sacc[2 * jp][3],
                        a0, a1, a2, a3, b00, b01);
                mma_f16(sacc[2 * jp + 1][0], sacc[2 * jp + 1][1],
                        sacc[2 * jp + 1][2], sacc[2 * jp + 1][3],
                        a0, a1, a2, a3, b10, b11);
            }
        }

#pragma unroll
        for (int r = 0; r < 2; r++) {
            float mx = -1e30f;
#pragma unroll
            for (int jn = 0; jn < 8; jn++) {
                mx = fmaxf(mx, sacc[jn][2 * r]);
                mx = fmaxf(mx, sacc[jn][2 * r + 1]);
            }
            mx = fmaxf(mx, __shfl_xor_sync(0xffffffffu, mx, 1));
            mx = fmaxf(mx, __shfl_xor_sync(0xffffffffu, mx, 2));
            float mnew = fmaxf(mrow[r], mx);
            float scale = __expf(mrow[r] - mnew);
            mrow[r] = mnew;
            float ps = 0.0f;
#pragma unroll
            for (int jn = 0; jn < 8; jn++) {
                float p0 = __expf(sacc[jn][2 * r] - mnew);
                float p1 = __expf(sacc[jn][2 * r + 1] - mnew);
                sacc[jn][2 * r] = p0;
                sacc[jn][2 * r + 1] = p1;
                ps += p0 + p1;
                oacc[jn][2 * r] *= scale;
                oacc[jn][2 * r + 1] *= scale;
            }
            lrow[r] = lrow[r] * scale + ps;
        }

#pragma unroll
        for (int kt = 0; kt < 4; kt++) {
            uint32_t a0 = pkh2(sacc[2 * kt][0], sacc[2 * kt][1]);
            uint32_t a1 = pkh2(sacc[2 * kt][2], sacc[2 * kt][3]);
            uint32_t a2 = pkh2(sacc[2 * kt + 1][0], sacc[2 * kt + 1][1]);
            uint32_t a3 = pkh2(sacc[2 * kt + 1][2], sacc[2 * kt + 1][3]);
            const int kp = ch * 32 + kt * 8;
#pragma unroll
            for (int jp = 0; jp < 4; jp++) {
                uint32_t b00, b01, b10, b11;
                ldsm4(b00, b01, b10, b11,
                      vt_b + ((16 * jp + b_n) * AV_ST + kp + b_k) * 4);
                mma_f16(oacc[2 * jp][0], oacc[2 * jp][1], oacc[2 * jp][2], oacc[2 * jp][3],
                        a0, a1, a2, a3, b00, b01);
                mma_f16(oacc[2 * jp + 1][0], oacc[2 * jp + 1][1],
                        oacc[2 * jp + 1][2], oacc[2 * jp + 1][3],
                        a0, a1, a2, a3, b10, b11);
            }
        }
    }

    float inv[2];
#pragma unroll
    for (int r = 0; r < 2; r++) {
        float lr = lrow[r];
        lr += __shfl_xor_sync(0xffffffffu, lr, 1);
        lr += __shfl_xor_sync(0xffffffffu, lr, 2);
        inv[r] = 1.0f / lr;
    }
    const size_t obase = (size_t)bj * SEQT * DIM + h * HD;
    __half* o0 = g_Oh + obase + (size_t)(m0 + grp) * DIM;
    __half* o1 = g_Oh + obase + (size_t)(m0 + grp + 8) * DIM;
#pragma unroll
    for (int jn = 0; jn < 8; jn++) {
        int col = 8 * jn + 2 * qd;
        *(uint32_t*)&o0[col] = pkh2(oacc[jn][0] * inv[0], oacc[jn][1] * inv[0]);
        *(uint32_t*)&o1[col] = pkh2(oacc[jn][2] * inv[1], oacc[jn][3] * inv[1]);
    }
}

// ---------------------------------------------------------------------------
// Kernel 3: output projection + bias, BK=64, 3-stage ring + ldmatrix.
// grid (4, 48)
// ---------------------------------------------------------------------------
__global__ __launch_bounds__(256, 2)
void proj_tc_kernel(const float* __restrict__ bo,
                    float* __restrict__ out)
{
    extern __shared__ uint32_t smem[];
    const uint32_t sbase = (uint32_t)__cvta_generic_to_shared(smem);

    const int nt = blockIdx.x;
    const int mt = blockIdx.y;

    const int tid  = threadIdx.x;
    const int wid  = tid >> 5;
    const int lane = tid & 31;
    const int wm   = (wid >> 2) * 64;
    const int wn   = (wid & 3) * 32;
    const int grp  = lane >> 2;
    const int qd   = lane & 3;

    const int a_row = (lane & 15);
    const int a_k   = 4 * (lane >> 4);
    const int b_n   = (lane & 7) + 8 * (lane >> 4);
    const int b_k   = 4 * ((lane >> 3) & 1);

    float acc[4][4][4];
#pragma unroll
    for (int i = 0; i < 4; i++)
#pragma unroll
        for (int jn = 0; jn < 4; jn++)
#pragma unroll
            for (int c = 0; c < 4; c++)
                acc[i][jn][c] = 0.0f;

    auto stage = [&](int kb, int bf) {
        uint32_t ab = sbase + bf * (STG_U * 4);
        uint32_t bb = ab + ABUF_U * 4;
#pragma unroll
        for (int l = 0; l < 4; l++) {
            int c   = tid + l * 256;
            int row = c >> 3;
            int cc  = c & 7;
            cpasync16(ab + row * (SAU * 4) + cc * 16,
                      g_Oh + (size_t)(mt * 128 + row) * DIM + kb * 64 + cc * 8);
            cpasync16(bb + row * (SAU * 4) + cc * 16,
                      g_Woh + (size_t)(nt * 128 + row) * DIM + kb * 64 + cc * 8);
        }
    };

    stage(0, 0);
    CP_COMMIT();
    stage(1, 1);
    CP_COMMIT();

    const int NKB = DIM / 64;   // 8
    for (int kb = 0; kb < NKB; kb++) {
        if (kb < NKB - 1) { CP_WAIT(1); } else { CP_WAIT(0); }
        __syncthreads();
        if (kb + 2 < NKB) {
            stage(kb + 2, (kb + 2) % 3);
            CP_COMMIT();
        }

        const uint32_t abase = sbase + (kb % 3) * (STG_U * 4);
        const uint32_t bbase = abase + ABUF_U * 4;

#pragma unroll
        for (int kk = 0; kk < 4; kk++) {
            const int kp = kk * 8;
            uint32_t a[4][4];
#pragma unroll
            for (int i = 0; i < 4; i++) {
                uint32_t addr = abase +
                    ((wm + 16 * i + a_row) * SAU + kp + a_k) * 4;
                ldsm4(a[i][0], a[i][1], a[i][2], a[i][3], addr);
            }
            uint32_t b[4][2];
#pragma unroll
            for (int jp = 0; jp < 2; jp++) {
                uint32_t addr = bbase +
                    ((wn + 16 * jp + b_n) * SAU + kp + b_k) * 4;
                ldsm4(b[2 * jp][0], b[2 * jp][1], b[2 * jp + 1][0], b[2 * jp + 1][1], addr);
            }
#pragma unroll
            for (int i = 0; i < 4; i++)
#pragma unroll
                for (int jn = 0; jn < 4; jn++)
                    mma_f16(acc[i][jn][0], acc[i][jn][1], acc[i][jn][2], acc[i][jn][3],
                            a[i][0], a[i][1], a[i][2], a[i][3],
                            b[jn][0], b[jn][1]);
        }
    }

    // Epilogue with bias, remap r=(b*NJ+j)*T+t -> [b][t][j][e]
#pragma unroll
    for (int i = 0; i < 4; i++) {
        int r = mt * 128 + wm + 16 * i + grp;
        int b = r / (NJ * SEQT);
        int rem = r - b * (NJ * SEQT);
        int jj = rem >> 8;
        int t  = rem & (SEQT - 1);
        size_t base0 = (((size_t)(b * SEQT + t) * NJ) + jj) * DIM + nt * 128 + wn;
        size_t base1 = base0 + (size_t)8 * NJ * DIM;
#pragma unroll
        for (int jn = 0; jn < 4; jn++) {
            int col = 8 * jn + 2 * qd;
            float2 bb = *(const float2*)(bo + nt * 128 + wn + col);
            *(float2*)&out[base0 + col] = make_float2(acc[i][jn][0] + bb.x,
                                                      acc[i][jn][1] + bb.y);
            *(float2*)&out[base1 + col] = make_float2(acc[i][jn][2] + bb.x,
                                                      acc[i][jn][3] + bb.y);
        }
    }
}

// ---------------------------------------------------------------------------
extern "C" void kernel_launch(void* const* d_in, const int* in_sizes, int n_in,
                              void* d_out, int out_size)
{
    const float* x  = (const float*)d_in[0];
    const float* Wq = (const float*)d_in[1];
    const float* Wk = (const float*)d_in[2];
    const float* Wv = (const float*)d_in[3];
    const float* Wo = (const float*)d_in[4];
    const float* bo = (const float*)d_in[5];
    float* out = (float*)d_out;

    void* xh;  cudaGetSymbolAddress(&xh,  g_Xh);
    void* woh; cudaGetSymbolAddress(&woh, g_Woh);

    // 0) pre-convert to half
    cvt_half_kernel<<<(QKV_ELEMS / 4 + 255) / 256, 256>>>(
        (const float4*)x, (uint2*)xh, QKV_ELEMS / 4);
    cvt_wt_kernel<<<dim3(16, 16, 72), dim3(32, 8)>>>(Wq, Wk, Wv);
    cvt_half_kernel<<<(DIM * DIM / 4 + 255) / 256, 256>>>(
        (const float4*)Wo, (uint2*)woh, DIM * DIM / 4);

    // 1) QKV projection (BK=64, 3-stage cp.async + ldmatrix, 2 CTAs/SM)
    cudaFuncSetAttribute(qkv_tc_kernel,
                         cudaFuncAttributeMaxDynamicSharedMemorySize, GEMM_SMEM);
    dim3 g1(DIM / 128, (BSZ * SEQT) / 128, 3 * NJ);   // (4, 16, 72)
    qkv_tc_kernel<<<g1, 256, GEMM_SMEM>>>();

    // 2) fp16 flash attention (ldmatrix)
    cudaFuncSetAttribute(attn_tc_kernel,
                         cudaFuncAttributeMaxDynamicSharedMemorySize, ATT_SMEM);
    attn_tc_kernel<<<BSZ * NJ * NH, 512, ATT_SMEM>>>();

    // 3) output projection + bias (BK=64, 3-stage + ldmatrix)
    cudaFuncSetAttribute(proj_tc_kernel,
                         cudaFuncAttributeMaxDynamicSharedMemorySize, GEMM_SMEM);
    dim3 g3(DIM / 128, (BSZ * SEQT * NJ) / 128);      // (4, 48)
    proj_tc_kernel<<<g3, 256, GEMM_SMEM>>>(bo, out);
}

// round 14
// speedup vs baseline: 2.9118x; 1.0316x over previous
#include <cuda_runtime.h>
#include <cuda_fp16.h>
#include <cstdint>

// Problem constants
#define BSZ 8
#define SEQT 256
#define NJ 24
#define DIM 512
#define NH 8
#define HD 64

#define QKV_ELEMS (BSZ * NJ * SEQT * DIM)  // 25,165,824
#define W_ELEMS   (NJ * DIM * DIM)         // 6,291,456

// fp16 operands / intermediates
__device__ __half g_Xh[QKV_ELEMS];       // x, layout [b][t][j][d]
__device__ __half g_Whq[W_ELEMS];        // W transposed: [j][n][k]
__device__ __half g_Whk[W_ELEMS];
__device__ __half g_Whv[W_ELEMS];
__device__ __half g_Woh[DIM * DIM];      // Wo [n][k]
__device__ __half g_Qh[QKV_ELEMS];       // Q pre-scaled by 0.125, [b][j][t][e]
__device__ __half g_Kh[QKV_ELEMS];       // K, [b][j][t][e]
__device__ __half g_Vth[QKV_ELEMS];      // V transposed, [b][j][e][t]
__device__ __half g_Oh[QKV_ELEMS];       // attention out, [b][j][t][e]

__device__ __forceinline__ uint32_t pkh2(float x, float y) {
    __half2 h = __float22half2_rn(make_float2(x, y));
    return *(uint32_t*)&h;
}

__device__ __forceinline__ void mma_f16(
    float& c0, float& c1, float& c2, float& c3,
    uint32_t a0, uint32_t a1, uint32_t a2, uint32_t a3,
    uint32_t b0, uint32_t b1)
{
    asm volatile(
        "mma.sync.aligned.m16n8k16.row.col.f32.f16.f16.f32 "
        "{%0,%1,%2,%3}, {%4,%5,%6,%7}, {%8,%9}, {%0,%1,%2,%3};\n"
        : "+f"(c0), "+f"(c1), "+f"(c2), "+f"(c3)
        : "r"(a0), "r"(a1), "r"(a2), "r"(a3), "r"(b0), "r"(b1));
}

__device__ __forceinline__ void ldsm4(uint32_t& r0, uint32_t& r1,
                                      uint32_t& r2, uint32_t& r3, uint32_t addr)
{
    asm volatile("ldmatrix.sync.aligned.m8n8.x4.shared.b16 {%0,%1,%2,%3}, [%4];"
                 : "=r"(r0), "=r"(r1), "=r"(r2), "=r"(r3) : "r"(addr));
}

__device__ __forceinline__ void cpasync16(uint32_t dst, const void* src) {
    asm volatile("cp.async.cg.shared.global [%0], [%1], 16;\n"
                 :: "r"(dst), "l"(src));
}
#define CP_COMMIT() asm volatile("cp.async.commit_group;\n" ::: "memory")
#define CP_WAIT(N)  asm volatile("cp.async.wait_group %0;\n" :: "n"(N) : "memory")

// ---------------------------------------------------------------------------
// Fused pre-pass: one launch converts x -> half, W{q,k,v} -> half transposed,
// Wo -> half. Block ranges: [0, XB) x-cvt, [XB, XB+WB) W-transpose, rest Wo.
// ---------------------------------------------------------------------------
#define XB   (QKV_ELEMS / 4 / 256)           // 24576
#define WTB  (16 * 16 * 72)                  // 18432
#define WOB  (DIM * DIM / 4 / 256)           // 256

__global__ __launch_bounds__(256)
void cvt_fused_kernel(const float4* __restrict__ x,
                      const float* __restrict__ Wq,
                      const float* __restrict__ Wk,
                      const float* __restrict__ Wv,
                      const float4* __restrict__ Wo)
{
    __shared__ float tile[32][33];
    const int bid = blockIdx.x;
    const int tid = threadIdx.x;

    if (bid < XB) {
        int i = bid * 256 + tid;
        float4 v = x[i];
        ((uint2*)g_Xh)[i] = make_uint2(pkh2(v.x, v.y), pkh2(v.z, v.w));
    } else if (bid < XB + WTB) {
        int r = bid - XB;
        int bx = r & 15;          // n-tile
        int by = (r >> 4) & 15;   // k-tile
        int z  = r >> 8;          // 0..71
        int j  = z % NJ;
        int p  = z / NJ;
        const float* W = (p == 0) ? Wq : ((p == 1) ? Wk : Wv);
        __half* Wh     = (p == 0) ? g_Whq : ((p == 1) ? g_Whk : g_Whv);
        int n0 = bx * 32, k0 = by * 32;
        int tx = tid & 31, ty = tid >> 5;
        const size_t base = (size_t)j * DIM * DIM;
#pragma unroll
        for (int i = 0; i < 4; i++)
            tile[ty + 8 * i][tx] = W[base + (size_t)(k0 + ty + 8 * i) * DIM + n0 + tx];
        __syncthreads();
#pragma unroll
        for (int i = 0; i < 4; i++)
            Wh[base + (size_t)(n0 + ty + 8 * i) * DIM + k0 + tx] =
                __float2half(tile[tx][ty + 8 * i]);
    } else {
        int i = (bid - XB - WTB) * 256 + tid;
        float4 v = Wo[i];
        ((uint2*)g_Woh)[i] = make_uint2(pkh2(v.x, v.y), pkh2(v.z, v.w));
    }
}

// ---------------------------------------------------------------------------
// Kernel 1: per-joint Q/K/V projection, fp16 m16n8k16, BK=32, 3-stage
// cp.async ring + ldmatrix (R11 geometry = fastest measured), plus smem-staged
// V transpose epilogue (kills the 16x sector write-amplification on g_Vth).
// Block 128x128, 256 threads, 2 CTAs/SM. grid: (4, 16, 72)
// ---------------------------------------------------------------------------
#define QSAU 20
#define QABUF_U (128 * QSAU)          // 2560 u32
#define QSTG_U  (2 * QABUF_U)         // 5120 u32 = 20480 B per stage
#define QKV_SMEM (3 * QSTG_U * 4)     // 61440 B (3-stage; also >= 34816 B for transpose)
#define TST 136                       // half-stride for [e][t] transpose rows (272 B, 16B mult)

__global__ __launch_bounds__(256, 2)
void qkv_tc_kernel()
{
    extern __shared__ uint32_t smem[];
    const uint32_t sbase = (uint32_t)__cvta_generic_to_shared(smem);

    const int nt = blockIdx.x;
    const int mt = blockIdx.y;
    const int z  = blockIdx.z;
    const int j  = z % NJ;
    const int p  = z / NJ;

    const __half* Wh = (p == 0) ? g_Whq : ((p == 1) ? g_Whk : g_Whv);

    const int tid  = threadIdx.x;
    const int wid  = tid >> 5;
    const int lane = tid & 31;
    const int wm   = (wid >> 2) * 64;
    const int wn   = (wid & 3) * 32;
    const int grp  = lane >> 2;
    const int qd   = lane & 3;

    const int a_row = (lane & 15);
    const int a_k   = 4 * (lane >> 4);
    const int b_n   = (lane & 7) + 8 * (lane >> 4);
    const int b_k   = 4 * ((lane >> 3) & 1);

    const size_t wbase = (size_t)j * DIM * DIM + (size_t)nt * 128 * DIM;

    float acc[4][4][4];
#pragma unroll
    for (int i = 0; i < 4; i++)
#pragma unroll
        for (int jn = 0; jn < 4; jn++)
#pragma unroll
            for (int c = 0; c < 4; c++)
                acc[i][jn][c] = 0.0f;

    auto stage = [&](int kb, int bf) {
        uint32_t ab = sbase + bf * (QSTG_U * 4);
        uint32_t bb = ab + QABUF_U * 4;
#pragma unroll
        for (int l = 0; l < 2; l++) {
            int c   = tid + l * 256;
            int row = c >> 2;
            int cc  = c & 3;
            cpasync16(ab + row * (QSAU * 4) + cc * 16,
                      g_Xh + ((size_t)(mt * 128 + row) * NJ + j) * DIM + kb * 32 + cc * 8);
            cpasync16(bb + row * (QSAU * 4) + cc * 16,
                      Wh + wbase + (size_t)row * DIM + kb * 32 + cc * 8);
        }
    };

    stage(0, 0);
    CP_COMMIT();
    stage(1, 1);
    CP_COMMIT();

    const int NKB = DIM / 32;   // 16
    for (int kb = 0; kb < NKB; kb++) {
        if (kb < NKB - 1) { CP_WAIT(1); } else { CP_WAIT(0); }
        __syncthreads();
        if (kb + 2 < NKB) {
            stage(kb + 2, (kb + 2) % 3);
            CP_COMMIT();
        }

        const uint32_t abase = sbase + (kb % 3) * (QSTG_U * 4);
        const uint32_t bbase = abase + QABUF_U * 4;

#pragma unroll
        for (int kk = 0; kk < 2; kk++) {
            const int kp = kk * 8;
            uint32_t a[4][4];
#pragma unroll
            for (int i = 0; i < 4; i++) {
                uint32_t addr = abase +
                    ((wm + 16 * i + a_row) * QSAU + kp + a_k) * 4;
                ldsm4(a[i][0], a[i][1], a[i][2], a[i][3], addr);
            }
            uint32_t b[4][2];
#pragma unroll
            for (int jp = 0; jp < 2; jp++) {
                uint32_t addr = bbase +
                    ((wn + 16 * jp + b_n) * QSAU + kp + b_k) * 4;
                ldsm4(b[2 * jp][0], b[2 * jp][1], b[2 * jp + 1][0], b[2 * jp + 1][1], addr);
            }
#pragma unroll
            for (int i = 0; i < 4; i++)
#pragma unroll
                for (int jn = 0; jn < 4; jn++)
                    mma_f16(acc[i][jn][0], acc[i][jn][1], acc[i][jn][2], acc[i][jn][3],
                            a[i][0], a[i][1], a[i][2], a[i][3],
                            b[jn][0], b[jn][1]);
        }
    }

    // Epilogue
    if (p < 2) {
        __half* outh = (p == 0) ? g_Qh : g_Kh;
        const float scl = (p == 0) ? 0.125f : 1.0f;
#pragma unroll
        for (int i = 0; i < 4; i++) {
            int m = mt * 128 + wm + 16 * i + grp;
            int b = m >> 8;
            int t = m & (SEQT - 1);
            size_t r0 = (((size_t)(b * NJ + j) * SEQT) + t) * DIM + nt * 128 + wn;
            size_t r1 = r0 + (size_t)8 * DIM;
#pragma unroll
            for (int jn = 0; jn < 4; jn++) {
                int col = 8 * jn + 2 * qd;
                *(uint32_t*)&outh[r0 + col] = pkh2(acc[i][jn][0] * scl, acc[i][jn][1] * scl);
                *(uint32_t*)&outh[r1 + col] = pkh2(acc[i][jn][2] * scl, acc[i][jn][3] * scl);
            }
        }
    } else {
        // V: transpose through smem, then coalesced 16B stores of Vt rows.
        __syncthreads();                       // mainloop smem is dead now
        __half* smT = (__half*)smem;           // [128 e][TST t]
#pragma unroll
        for (int i = 0; i < 4; i++) {
            int tl0 = wm + 16 * i + grp;       // local t 0..127
            int tl1 = tl0 + 8;
#pragma unroll
            for (int jn = 0; jn < 4; jn++) {
                int e0 = wn + 8 * jn + 2 * qd; // local e
                smT[e0 * TST + tl0]       = __float2half(acc[i][jn][0]);
                smT[(e0 + 1) * TST + tl0] = __float2half(acc[i][jn][1]);
                smT[e0 * TST + tl1]       = __float2half(acc[i][jn][2]);
                smT[(e0 + 1) * TST + tl1] = __float2half(acc[i][jn][3]);
            }
        }
        __syncthreads();
        // 128 e-rows x 128 t halves = 2048 uint4; t contiguous (single b per CTA)
        const int b  = (mt * 128) >> 8;
        const int t0 = (mt * 128) & (SEQT - 1);
        const size_t gb = ((size_t)(b * NJ + j) * DIM + nt * 128) * SEQT + t0;
#pragma unroll
        for (int l = 0; l < 8; l++) {
            int idx = tid + l * 256;
            int e   = idx >> 4;
            int q4  = idx & 15;
            uint4 v = *(uint4*)&smT[e * TST + q4 * 8];
            *(uint4*)&g_Vth[gb + (size_t)e * SEQT + q4 * 8] = v;
        }
    }
}

// ---------------------------------------------------------------------------
// Kernel 2: fp16 flash attention with ldmatrix (R12-verbatim).
// ---------------------------------------------------------------------------
#define AQ_ST 36
#define AV_ST 132
#define ATT_U (2 * SEQT * AQ_ST + HD * AV_ST)
#define ATT_SMEM (ATT_U * 4)

__global__ __launch_bounds__(512)
void attn_tc_kernel()
{
    extern __shared__ uint32_t smu[];
    const uint32_t sbase = (uint32_t)__cvta_generic_to_shared(smu);
    const uint32_t qs_b = sbase;
    const uint32_t ks_b = sbase + SEQT * AQ_ST * 4;
    const uint32_t vt_b = sbase + 2 * SEQT * AQ_ST * 4;

    const int bjh = blockIdx.x;
    const int h   = bjh & (NH - 1);
    const int bj  = bjh >> 3;
    const int tid  = threadIdx.x;
    const int wid  = tid >> 5;
    const int lane = tid & 31;
    const int grp  = lane >> 2;
    const int qd   = lane & 3;
    const int m0   = wid * 16;

    const int a_row = (lane & 15);
    const int a_k   = 4 * (lane >> 4);
    const int b_n   = (lane & 7) + 8 * (lane >> 4);
    const int b_k   = 4 * ((lane >> 3) & 1);

    const __half* qg = g_Qh + (size_t)bj * SEQT * DIM + h * HD;
    const __half* kg = g_Kh + (size_t)bj * SEQT * DIM + h * HD;
    const __half* vg = g_Vth + (size_t)bj * DIM * SEQT + (size_t)h * HD * SEQT;

#pragma unroll
    for (int l = 0; l < 4; l++) {
        int idx = tid + l * 512;
        int row = idx >> 3;
        int q4  = idx & 7;
        cpasync16(qs_b + (row * AQ_ST + q4 * 4) * 4, qg + (size_t)row * DIM + q4 * 8);
        cpasync16(ks_b + (row * AQ_ST + q4 * 4) * 4, kg + (size_t)row * DIM + q4 * 8);
    }
#pragma unroll
    for (int l = 0; l < 4; l++) {
        int idx = tid + l * 512;
        int d  = idx >> 5;
        int q4 = idx & 31;
        cpasync16(vt_b + (d * AV_ST + q4 * 4) * 4, vg + (size_t)d * SEQT + q4 * 8);
    }
    CP_COMMIT();
    CP_WAIT(0);
    __syncthreads();

    float oacc[8][4];
#pragma unroll
    for (int jn = 0; jn < 8; jn++)
#pragma unroll
        for (int c = 0; c < 4; c++) oacc[jn][c] = 0.0f;
    float mrow[2] = { -1e30f, -1e30f };
    float lrow[2] = { 0.0f, 0.0f };

    for (int ch = 0; ch < 4; ch++) {
        float sacc[8][4];
#pragma unroll
        for (int jn = 0; jn < 8; jn++)
#pragma unroll
            for (int c = 0; c < 4; c++) sacc[jn][c] = 0.0f;

#pragma unroll
        for (int kt = 0; kt < 4; kt++) {
            const int kp = kt * 8;
            uint32_t a0, a1, a2, a3;
            ldsm4(a0, a1, a2, a3,
                  qs_b + ((m0 + a_row) * AQ_ST + kp + a_k) * 4);
#pragma unroll
            for (int jp = 0; jp < 4; jp++) {
                uint32_t b00, b01, b10, b11;
                ldsm4(b00, b01, b10, b11,
                      ks_b + ((ch * 64 + 16 * jp + b_n) * AQ_ST + kp + b_k) * 4);
                mma_f16(sacc[2 * jp][0], sacc[2 * jp][1], sacc[2 * jp][2], sacc[2 * jp][3],
                        a0, a1, a2, a3, b00, b01);
                mma_f16(sacc[2 * jp + 1][0], sacc[2 * jp + 1][1],
                        sacc[2 * jp + 1][2], sacc[2 * jp + 1][3],
                        a0, a1, a2, a3, b10, b11);
            }
        }

#pragma unroll
        for (int r = 0; r < 2; r++) {
            float mx = -1e30f;
#pragma unroll
            for (int jn = 0; jn < 8; jn++) {
                mx = fmaxf(mx, sacc[jn][2 * r]);
                mx = fmaxf(mx, sacc[jn][2 * r + 1]);
            }
            mx = fmaxf(mx, __shfl_xor_sync(0xffffffffu, mx, 1));
            mx = fmaxf(mx, __shfl_xor_sync(0xffffffffu, mx, 2));
            float mnew = fmaxf(mrow[r], mx);
            float scale = __expf(mrow[r] - mnew);
            mrow[r] = mnew;
            float ps = 0.0f;
#pragma unroll
            for (int jn = 0; jn < 8; jn++) {
                float p0 = __expf(sacc[jn][2 * r] - mnew);
                float p1 = __expf(sacc[jn][2 * r + 1] - mnew);
                sacc[jn][2 * r] = p0;
                sacc[jn][2 * r + 1] = p1;
                ps += p0 + p1;
                oacc[jn][2 * r] *= scale;
                oacc[jn][2 * r + 1] *= scale;
            }
            lrow[r] = lrow[r] * scale + ps;
        }

#pragma unroll
        for (int kt = 0; kt < 4; kt++) {
            uint32_t a0 = pkh2(sacc[2 * kt][0], sacc[2 * kt][1]);
            uint32_t a1 = pkh2(sacc[2 * kt][2], sacc[2 * kt][3]);
            uint32_t a2 = pkh2(sacc[2 * kt + 1][0], sacc[2 * kt + 1][1]);
            uint32_t a3 = pkh2(sacc[2 * kt + 1][2], sacc[2 * kt + 1][3]);
            const int kp = ch * 32 + kt * 8;
#pragma unroll
            for (int jp = 0; jp < 4; jp++) {
                uint32_t b00, b01, b10, b11;
                ldsm4(b00, b01, b10, b11,
                      vt_b + ((16 * jp + b_n) * AV_ST + kp + b_k) * 4);
                mma_f16(oacc[2 * jp][0], oacc[2 * jp][1], oacc[2 * jp][2], oacc[2 * jp][3],
                        a0, a1, a2, a3, b00, b01);
                mma_f16(oacc[2 * jp + 1][0], oacc[2 * jp + 1][1],
                        oacc[2 * jp + 1][2], oacc[2 * jp + 1][3],
                        a0, a1, a2, a3, b10, b11);
            }
        }
    }

    float inv[2];
#pragma unroll
    for (int r = 0; r < 2; r++) {
        float lr = lrow[r];
        lr += __shfl_xor_sync(0xffffffffu, lr, 1);
        lr += __shfl_xor_sync(0xffffffffu, lr, 2);
        inv[r] = 1.0f / lr;
    }
    const size_t obase = (size_t)bj * SEQT * DIM + h * HD;
    __half* o0 = g_Oh + obase + (size_t)(m0 + grp) * DIM;
    __half* o1 = g_Oh + obase + (size_t)(m0 + grp + 8) * DIM;
#pragma unroll
    for (int jn = 0; jn < 8; jn++) {
        int col = 8 * jn + 2 * qd;
        *(uint32_t*)&o0[col] = pkh2(oacc[jn][0] * inv[0], oacc[jn][1] * inv[0]);
        *(uint32_t*)&o1[col] = pkh2(oacc[jn][2] * inv[1], oacc[jn][3] * inv[1]);
    }
}

// ---------------------------------------------------------------------------
// Kernel 3: output projection + bias, BK=64, 3-stage ring + ldmatrix
// (R12-verbatim).
// ---------------------------------------------------------------------------
#define PSAU 36
#define PABUF_U (128 * PSAU)
#define PSTG_U  (2 * PABUF_U)
#define PROJ_SMEM (3 * PSTG_U * 4)

__global__ __launch_bounds__(256, 2)
void proj_tc_kernel(const float* __restrict__ bo,
                    float* __restrict__ out)
{
    extern __shared__ uint32_t smem[];
    const uint32_t sbase = (uint32_t)__cvta_generic_to_shared(smem);

    const int nt = blockIdx.x;
    const int mt = blockIdx.y;

    const int tid  = threadIdx.x;
    const int wid  = tid >> 5;
    const int lane = tid & 31;
    const int wm   = (wid >> 2) * 64;
    const int wn   = (wid & 3) * 32;
    const int grp  = lane >> 2;
    const int qd   = lane & 3;

    const int a_row = (lane & 15);
    const int a_k   = 4 * (lane >> 4);
    const int b_n   = (lane & 7) + 8 * (lane >> 4);
    const int b_k   = 4 * ((lane >> 3) & 1);

    float acc[4][4][4];
#pragma unroll
    for (int i = 0; i < 4; i++)
#pragma unroll
        for (int jn = 0; jn < 4; jn++)
#pragma unroll
            for (int c = 0; c < 4; c++)
                acc[i][jn][c] = 0.0f;

    auto stage = [&](int kb, int bf) {
        uint32_t ab = sbase + bf * (PSTG_U * 4);
        uint32_t bb = ab + PABUF_U * 4;
#pragma unroll
        for (int l = 0; l < 4; l++) {
            int c   = tid + l * 256;
            int row = c >> 3;
            int cc  = c & 7;
            cpasync16(ab + row * (PSAU * 4) + cc * 16,
                      g_Oh + (size_t)(mt * 128 + row) * DIM + kb * 64 + cc * 8);
            cpasync16(bb + row * (PSAU * 4) + cc * 16,
                      g_Woh + (size_t)(nt * 128 + row) * DIM + kb * 64 + cc * 8);
        }
    };

    stage(0, 0);
    CP_COMMIT();
    stage(1, 1);
    CP_COMMIT();

    const int NKB = DIM / 64;
    for (int kb = 0; kb < NKB; kb++) {
        if (kb < NKB - 1) { CP_WAIT(1); } else { CP_WAIT(0); }
        __syncthreads();
        if (kb + 2 < NKB) {
            stage(kb + 2, (kb + 2) % 3);
            CP_COMMIT();
        }

        const uint32_t abase = sbase + (kb % 3) * (PSTG_U * 4);
        const uint32_t bbase = abase + PABUF_U * 4;

#pragma unroll
        for (int kk = 0; kk < 4; kk++) {
            const int kp = kk * 8;
            uint32_t a[4][4];
#pragma unroll
            for (int i = 0; i < 4; i++) {
                uint32_t addr = abase +
                    ((wm + 16 * i + a_row) * PSAU + kp + a_k) * 4;
                ldsm4(a[i][0], a[i][1], a[i][2], a[i][3], addr);
            }
            uint32_t b[4][2];
#pragma unroll
            for (int jp = 0; jp < 2; jp++) {
                uint32_t addr = bbase +
                    ((wn + 16 * jp + b_n) * PSAU + kp + b_k) * 4;
                ldsm4(b[2 * jp][0], b[2 * jp][1], b[2 * jp + 1][0], b[2 * jp + 1][1], addr);
            }
#pragma unroll
            for (int i = 0; i < 4; i++)
#pragma unroll
                for (int jn = 0; jn < 4; jn++)
                    mma_f16(acc[i][jn][0], acc[i][jn][1], acc[i][jn][2], acc[i][jn][3],
                            a[i][0], a[i][1], a[i][2], a[i][3],
                            b[jn][0], b[jn][1]);
        }
    }

#pragma unroll
    for (int i = 0; i < 4; i++) {
        int r = mt * 128 + wm + 16 * i + grp;
        int b = r / (NJ * SEQT);
        int rem = r - b * (NJ * SEQT);
        int jj = rem >> 8;
        int t  = rem & (SEQT - 1);
        size_t base0 = (((size_t)(b * SEQT + t) * NJ) + jj) * DIM + nt * 128 + wn;
        size_t base1 = base0 + (size_t)8 * NJ * DIM;
#pragma unroll
        for (int jn = 0; jn < 4; jn++) {
            int col = 8 * jn + 2 * qd;
            float2 bb = *(const float2*)(bo + nt * 128 + wn + col);
            *(float2*)&out[base0 + col] = make_float2(acc[i][jn][0] + bb.x,
                                                      acc[i][jn][1] + bb.y);
            *(float2*)&out[base1 + col] = make_float2(acc[i][jn][2] + bb.x,
                                                      acc[i][jn][3] + bb.y);
        }
    }
}

// ---------------------------------------------------------------------------
extern "C" void kernel_launch(void* const* d_in, const int* in_sizes, int n_in,
                              void* d_out, int out_size)
{
    const float* x  = (const float*)d_in[0];
    const float* Wq = (const float*)d_in[1];
    const float* Wk = (const float*)d_in[2];
    const float* Wv = (const float*)d_in[3];
    const float* Wo = (const float*)d_in[4];
    const float* bo = (const float*)d_in[5];
    float* out = (float*)d_out;

    // 0) fused pre-convert (one launch)
    cvt_fused_kernel<<<XB + WTB + WOB, 256>>>(
        (const float4*)x, Wq, Wk, Wv, (const float4*)Wo);

    // 1) QKV projection (BK=32, 3-stage cp.async + ldmatrix, smem V-transpose)
    cudaFuncSetAttribute(qkv_tc_kernel,
                         cudaFuncAttributeMaxDynamicSharedMemorySize, QKV_SMEM);
    dim3 g1(DIM / 128, (BSZ * SEQT) / 128, 3 * NJ);   // (4, 16, 72)
    qkv_tc_kernel<<<g1, 256, QKV_SMEM>>>();

    // 2) fp16 flash attention (ldmatrix)
    cudaFuncSetAttribute(attn_tc_kernel,
                         cudaFuncAttributeMaxDynamicSharedMemorySize, ATT_SMEM);
    attn_tc_kernel<<<BSZ * NJ * NH, 512, ATT_SMEM>>>();

    // 3) output projection + bias (BK=64, 3-stage + ldmatrix)
    cudaFuncSetAttribute(proj_tc_kernel,
                         cudaFuncAttributeMaxDynamicSharedMemorySize, PROJ_SMEM);
    dim3 g3(DIM / 128, (BSZ * SEQT * NJ) / 128);      // (4, 48)
    proj_tc_kernel<<<g3, 256, PROJ_SMEM>>>(bo, out);
}